// round 7
// baseline (speedup 1.0000x reference)
#include <cuda_runtime.h>
#include <cstdint>

#define NPTS   131072          // B*N = 2*65536
#define EPSBN  1e-5f

// ---- folded params + scratch (device globals; no allocation) ----
__device__ float  d_wraw[10*32];
__device__ float  d_braw[32];
__device__ float2 d_wnbt2[32*32];   // w_nb rows 0..31 (feature part), pair (c, c+32)
__device__ float2 d_wnbb2[32*32];   // w_nb rows 32..63 (raw_mlp part)
__device__ float2 d_bnb2[32];
__device__ float2 d_wattn2[64*32];
__device__ float2 d_wout2[64*32];
__device__ float2 d_bout2[32];
__device__ float2 d_wsc2[32*32];
__device__ float2 d_bsc2[32];
__device__ float2 d_G2[(size_t)NPTS*32];   // G = feature @ W_nb_top'  (~33.5MB, L2-resident)

union F2U { float2 f; unsigned long long u; };

__device__ __forceinline__ unsigned long long packdup(float a){
    unsigned long long r; asm("mov.b64 %0, {%1, %1};" : "=l"(r) : "f"(a)); return r;
}
__device__ __forceinline__ void ffma2(unsigned long long& d, unsigned long long a, unsigned long long b){
    asm("fma.rn.f32x2 %0, %1, %2, %0;" : "+l"(d) : "l"(a), "l"(b));
}
__device__ __forceinline__ float lrelu(float x){ return fmaxf(x, 0.2f*x); }

// ---- Kernel 0: fold BN into weights. 32 threads. ----
__global__ void fold_kernel(
    const float* w_raw, const float* b_raw, const float* g_raw, const float* be_raw,
    const float* m_raw, const float* v_raw,
    const float* w_nb,  const float* b_nb,  const float* g_nb,  const float* be_nb,
    const float* m_nb,  const float* v_nb,  const float* w_attn,
    const float* w_out, const float* b_out, const float* g_out, const float* be_out,
    const float* m_out, const float* v_out,
    const float* w_sc,  const float* b_sc,  const float* g_sc,  const float* be_sc,
    const float* m_sc,  const float* v_sc)
{
    const int p = threadIdx.x; if (p >= 32) return;
    float sr = g_raw[p]*rsqrtf(v_raw[p]+EPSBN);
    for (int k=0;k<10;k++) d_wraw[k*32+p] = w_raw[k*32+p]*sr;
    d_braw[p] = (b_raw[p]-m_raw[p])*sr + be_raw[p];

    float s0 = g_nb[p]*rsqrtf(v_nb[p]+EPSBN);
    float s1 = g_nb[p+32]*rsqrtf(v_nb[p+32]+EPSBN);
    for (int k=0;k<32;k++)
        d_wnbt2[k*32+p] = make_float2(w_nb[k*64+p]*s0, w_nb[k*64+p+32]*s1);
    for (int j=0;j<32;j++)
        d_wnbb2[j*32+p] = make_float2(w_nb[(32+j)*64+p]*s0, w_nb[(32+j)*64+p+32]*s1);
    d_bnb2[p] = make_float2((b_nb[p]-m_nb[p])*s0+be_nb[p], (b_nb[p+32]-m_nb[p+32])*s1+be_nb[p+32]);

    for (int k=0;k<64;k++)
        d_wattn2[k*32+p] = make_float2(w_attn[k*64+p], w_attn[k*64+p+32]);

    float so0 = g_out[p]*rsqrtf(v_out[p]+EPSBN);
    float so1 = g_out[p+32]*rsqrtf(v_out[p+32]+EPSBN);
    for (int k=0;k<64;k++)
        d_wout2[k*32+p] = make_float2(w_out[k*64+p]*so0, w_out[k*64+p+32]*so1);
    d_bout2[p] = make_float2((b_out[p]-m_out[p])*so0+be_out[p], (b_out[p+32]-m_out[p+32])*so1+be_out[p+32]);

    float ss0 = g_sc[p]*rsqrtf(v_sc[p]+EPSBN);
    float ss1 = g_sc[p+32]*rsqrtf(v_sc[p+32]+EPSBN);
    for (int k=0;k<32;k++)
        d_wsc2[k*32+p] = make_float2(w_sc[k*64+p]*ss0, w_sc[k*64+p+32]*ss1);
    d_bsc2[p] = make_float2((b_sc[p]-m_sc[p])*ss0+be_sc[p], (b_sc[p+32]-m_sc[p+32])*ss1+be_sc[p+32]);
}

// ---- Kernel 1: G = feature @ W_nb_top'. One warp per point. ----
__global__ void __launch_bounds__(256) g_kernel(const float* __restrict__ feature)
{
    __shared__ float2 sw[32*32];
    for (int i = threadIdx.x; i < 1024; i += 256) sw[i] = d_wnbt2[i];
    __syncthreads();
    const int g = blockIdx.x*256 + threadIdx.x;
    const int pt = g >> 5, lane = g & 31;
    const float f = feature[pt*32 + lane];
    F2U acc; acc.f = make_float2(0.f, 0.f);
    #pragma unroll
    for (int k=0;k<32;k++){
        F2U w; w.f = sw[k*32+lane];
        ffma2(acc.u, packdup(__shfl_sync(0xffffffffu, f, k)), w.u);
    }
    d_G2[(size_t)pt*32 + lane] = acc.f;
}

// ---- Kernel 2: fused main. One warp/point; lane tile 4 rows x 4 pairs. ----
__global__ void __launch_bounds__(128) main_kernel(
    const float* __restrict__ feature,
    const float* __restrict__ raw,
    const int*   __restrict__ nbr,
    float*       __restrict__ outp)
{
    __shared__ float2 sh_wnbb[32*32];    // 8 KB
    __shared__ float2 sh_wattn[64*32];   // 16 KB
    __shared__ float4 sh_st[4][256];     // 16 KB (rm-T, then h-T, per warp)
    __shared__ float2 sh_pool[4][32];    // 1 KB

    const int tid = threadIdx.x;
    for (int i = tid; i < 32*32; i += 128) sh_wnbb[i]  = d_wnbb2[i];
    for (int i = tid; i < 64*32; i += 128) sh_wattn[i] = d_wattn2[i];
    __syncthreads();

    const int lane = tid & 31, w = tid >> 5;
    const int mt = lane >> 3;      // row tile: rows 4mt..4mt+3
    const int ct = lane & 7;       // pair tile: pairs 4ct..4ct+3
    float4* const st   = sh_st[w];
    float2* const pool = sh_pool[w];

    const int pt = blockIdx.x*4 + w;
    const int bbase = (pt >> 16) << 16;           // batch offset (N=65536)

    // neighbor indices
    int idxv = 0;
    if (lane < 16) idxv = nbr[pt*16 + lane];

    // early G gathers (L2): rows 4mt+r, pairs 4ct..4ct+3
    F2U g2[4][4];
    #pragma unroll
    for (int r=0;r<4;r++){
        int j = __shfl_sync(0xffffffffu, idxv, 4*mt + r);
        const float2* gp = d_G2 + ((size_t)(bbase + j)*32 + 4*ct);
        float4 lo = *(const float4*)gp;
        float4 hi = *(const float4*)(gp + 2);
        g2[r][0].f = make_float2(lo.x, lo.y); g2[r][1].f = make_float2(lo.z, lo.w);
        g2[r][2].f = make_float2(hi.x, hi.y); g2[r][3].f = make_float2(hi.z, hi.w);
    }

    // raw features: 160 floats per point
    float rv[5];
    #pragma unroll
    for (int i=0;i<5;i++) rv[i] = raw[pt*160 + i*32 + lane];

    // raw_mlp: lane owns column c=lane for all 16 rows
    float wr[10];
    #pragma unroll
    for (int k=0;k<10;k++) wr[k] = d_wraw[k*32 + lane];
    const float braw_l = d_braw[lane];
    float rm[16];
    #pragma unroll
    for (int m=0;m<16;m++){
        float acc = braw_l;
        #pragma unroll
        for (int k=0;k<10;k++){
            const int f = m*10 + k;
            acc = fmaf(__shfl_sync(0xffffffffu, rv[f>>5], f&31), wr[k], acc);
        }
        rm[m] = lrelu(acc);
    }

    // stage rm transposed: st[j*4+t] = rows 4t..4t+3 of column j
    __syncwarp();
    #pragma unroll
    for (int t=0;t<4;t++)
        st[lane*4 + t] = make_float4(rm[4*t], rm[4*t+1], rm[4*t+2], rm[4*t+3]);
    __syncwarp();

    // R = raw_mlp @ W_nb_bot' + b_nb'  (K=32)
    F2U acc2[4][4];
    #pragma unroll
    for (int r=0;r<4;r++)
        #pragma unroll
        for (int i=0;i<4;i++) acc2[r][i].f = d_bnb2[4*ct + i];

    #pragma unroll 4
    for (int j=0;j<32;j++){
        float4 a4 = st[j*4 + mt];
        ulonglong2 b01 = *(const ulonglong2*)(sh_wnbb + j*32 + 4*ct);
        ulonglong2 b23 = *(const ulonglong2*)(sh_wnbb + j*32 + 4*ct + 2);
        float av[4] = {a4.x, a4.y, a4.z, a4.w};
        #pragma unroll
        for (int r=0;r<4;r++){
            unsigned long long ad = packdup(av[r]);
            ffma2(acc2[r][0].u, ad, b01.x); ffma2(acc2[r][1].u, ad, b01.y);
            ffma2(acc2[r][2].u, ad, b23.x); ffma2(acc2[r][3].u, ad, b23.y);
        }
    }

    // h = lrelu(G_gathered + R)
    float2 h2[4][4];
    #pragma unroll
    for (int r=0;r<4;r++)
        #pragma unroll
        for (int i=0;i<4;i++)
            h2[r][i] = make_float2(lrelu(acc2[r][i].f.x + g2[r][i].f.x),
                                   lrelu(acc2[r][i].f.y + g2[r][i].f.y));

    // stage h transposed over channels
    __syncwarp();
    #pragma unroll
    for (int i=0;i<4;i++){
        st[(4*ct+i)*4 + mt]    = make_float4(h2[0][i].x, h2[1][i].x, h2[2][i].x, h2[3][i].x);
        st[(4*ct+i+32)*4 + mt] = make_float4(h2[0][i].y, h2[1][i].y, h2[2][i].y, h2[3][i].y);
    }
    __syncwarp();

    // s = h @ w_attn  (K=64)
    F2U s2[4][4];
    #pragma unroll
    for (int r=0;r<4;r++)
        #pragma unroll
        for (int i=0;i<4;i++) s2[r][i].f = make_float2(0.f, 0.f);

    #pragma unroll 4
    for (int k=0;k<64;k++){
        float4 a4 = st[k*4 + mt];
        ulonglong2 b01 = *(const ulonglong2*)(sh_wattn + k*32 + 4*ct);
        ulonglong2 b23 = *(const ulonglong2*)(sh_wattn + k*32 + 4*ct + 2);
        float av[4] = {a4.x, a4.y, a4.z, a4.w};
        #pragma unroll
        for (int r=0;r<4;r++){
            unsigned long long ad = packdup(av[r]);
            ffma2(s2[r][0].u, ad, b01.x); ffma2(s2[r][1].u, ad, b01.y);
            ffma2(s2[r][2].u, ad, b23.x); ffma2(s2[r][3].u, ad, b23.y);
        }
    }

    // softmax over 16 rows (split across lanes {ct, ct+8, ct+16, ct+24}) + pooling
    float px[4], py[4];
    #pragma unroll
    for (int i=0;i<4;i++){
        float mx = fmaxf(fmaxf(s2[0][i].f.x, s2[1][i].f.x), fmaxf(s2[2][i].f.x, s2[3][i].f.x));
        float my = fmaxf(fmaxf(s2[0][i].f.y, s2[1][i].f.y), fmaxf(s2[2][i].f.y, s2[3][i].f.y));
        mx = fmaxf(mx, __shfl_xor_sync(0xffffffffu, mx, 8));
        mx = fmaxf(mx, __shfl_xor_sync(0xffffffffu, mx, 16));
        my = fmaxf(my, __shfl_xor_sync(0xffffffffu, my, 8));
        my = fmaxf(my, __shfl_xor_sync(0xffffffffu, my, 16));
        float sx = 0.f, sy = 0.f, pxx = 0.f, pyy = 0.f;
        #pragma unroll
        for (int r=0;r<4;r++){
            float ex = __expf(s2[r][i].f.x - mx);
            float ey = __expf(s2[r][i].f.y - my);
            sx += ex; sy += ey;
            pxx = fmaf(ex, h2[r][i].x, pxx);
            pyy = fmaf(ey, h2[r][i].y, pyy);
        }
        sx += __shfl_xor_sync(0xffffffffu, sx, 8);  sx += __shfl_xor_sync(0xffffffffu, sx, 16);
        sy += __shfl_xor_sync(0xffffffffu, sy, 8);  sy += __shfl_xor_sync(0xffffffffu, sy, 16);
        pxx += __shfl_xor_sync(0xffffffffu, pxx, 8); pxx += __shfl_xor_sync(0xffffffffu, pxx, 16);
        pyy += __shfl_xor_sync(0xffffffffu, pyy, 8); pyy += __shfl_xor_sync(0xffffffffu, pyy, 16);
        px[i] = pxx / sx; py[i] = pyy / sy;
    }
    __syncwarp();
    if (mt == 0){
        #pragma unroll
        for (int i=0;i<4;i++) pool[4*ct+i] = make_float2(px[i], py[i]);
    }
    __syncwarp();

    // out = pooled @ w_out' + b_out'; sc = feature @ w_sc' + b_sc'; result = lrelu(sc+out)
    F2U oacc; oacc.f = d_bout2[lane];
    #pragma unroll 8
    for (int p=0;p<32;p++){
        float2 pv = pool[p];
        F2U w0; w0.f = d_wout2[p*32 + lane];
        F2U w1; w1.f = d_wout2[(p+32)*32 + lane];
        ffma2(oacc.u, packdup(pv.x), w0.u);
        ffma2(oacc.u, packdup(pv.y), w1.u);
    }

    F2U sacc; sacc.f = d_bsc2[lane];
    const float fv = feature[pt*32 + lane];
    #pragma unroll 8
    for (int k=0;k<32;k++){
        F2U w; w.f = d_wsc2[k*32 + lane];
        ffma2(sacc.u, packdup(__shfl_sync(0xffffffffu, fv, k)), w.u);
    }

    outp[pt*64 + lane]      = lrelu(sacc.f.x + oacc.f.x);
    outp[pt*64 + lane + 32] = lrelu(sacc.f.y + oacc.f.y);
}

extern "C" void kernel_launch(void* const* d_in, const int* in_sizes, int n_in,
                              void* d_out, int out_size)
{
    const float* feature = (const float*)d_in[0];
    const float* raw     = (const float*)d_in[1];
    const int*   nbr     = (const int*)  d_in[2];

    fold_kernel<<<1, 32>>>(
        (const float*)d_in[3],  (const float*)d_in[4],  (const float*)d_in[5],
        (const float*)d_in[6],  (const float*)d_in[7],  (const float*)d_in[8],
        (const float*)d_in[9],  (const float*)d_in[10], (const float*)d_in[11],
        (const float*)d_in[12], (const float*)d_in[13], (const float*)d_in[14],
        (const float*)d_in[15],
        (const float*)d_in[16], (const float*)d_in[17], (const float*)d_in[18],
        (const float*)d_in[19], (const float*)d_in[20], (const float*)d_in[21],
        (const float*)d_in[22], (const float*)d_in[23], (const float*)d_in[24],
        (const float*)d_in[25], (const float*)d_in[26], (const float*)d_in[27]);

    g_kernel<<<(NPTS*32)/256, 256>>>(feature);

    main_kernel<<<NPTS/4, 128>>>(feature, raw, nbr, (float*)d_out);
}

// round 8
// speedup vs baseline: 1.0064x; 1.0064x over previous
#include <cuda_runtime.h>
#include <cstdint>

#define NPTS   131072          // B*N = 2*65536
#define EPSBN  1e-5f

// ---- folded params + scratch (device globals; no allocation) ----
__device__ float  d_wraw[10*32];
__device__ float  d_braw[32];
__device__ float2 d_wnbt2[32*32];   // w_nb rows 0..31 (feature part), pair (c, c+32)
__device__ float2 d_wnbb2[32*32];   // w_nb rows 32..63 (raw_mlp part)
__device__ float2 d_bnb2[32];
__device__ float2 d_wattn2[64*32];
__device__ float2 d_wout2[64*32];
__device__ float2 d_bout2[32];
__device__ float2 d_wsc2[32*32];
__device__ float2 d_bsc2[32];
__device__ float2 d_G2[(size_t)NPTS*32];   // G = feature @ W_nb_top'  (~33.5MB, L2-resident)

union F2U { float2 f; unsigned long long u; };

__device__ __forceinline__ unsigned long long packdup(float a){
    unsigned long long r; asm("mov.b64 %0, {%1, %1};" : "=l"(r) : "f"(a)); return r;
}
__device__ __forceinline__ void ffma2(unsigned long long& d, unsigned long long a, unsigned long long b){
    asm("fma.rn.f32x2 %0, %1, %2, %0;" : "+l"(d) : "l"(a), "l"(b));
}
__device__ __forceinline__ float lrelu(float x){ return fmaxf(x, 0.2f*x); }

// ---- Kernel 0: fold BN into weights. Parallel (1024 threads). ----
__global__ void __launch_bounds__(1024) fold_kernel(
    const float* w_raw, const float* b_raw, const float* g_raw, const float* be_raw,
    const float* m_raw, const float* v_raw,
    const float* w_nb,  const float* b_nb,  const float* g_nb,  const float* be_nb,
    const float* m_nb,  const float* v_nb,  const float* w_attn,
    const float* w_out, const float* b_out, const float* g_out, const float* be_out,
    const float* m_out, const float* v_out,
    const float* w_sc,  const float* b_sc,  const float* g_sc,  const float* be_sc,
    const float* m_sc,  const float* v_sc)
{
    const int t = threadIdx.x;

    // raw mlp weights: 320 elements
    if (t < 320) {
        int k = t / 32, p = t % 32;
        float sr = g_raw[p]*rsqrtf(v_raw[p]+EPSBN);
        d_wraw[k*32+p] = w_raw[k*32+p]*sr;
    }
    // nb weights (top/bottom): 1024 elements each
    {
        int k = t / 32, p = t % 32;
        float s0 = g_nb[p]*rsqrtf(v_nb[p]+EPSBN);
        float s1 = g_nb[p+32]*rsqrtf(v_nb[p+32]+EPSBN);
        d_wnbt2[k*32+p] = make_float2(w_nb[k*64+p]*s0, w_nb[k*64+p+32]*s1);
        d_wnbb2[k*32+p] = make_float2(w_nb[(32+k)*64+p]*s0, w_nb[(32+k)*64+p+32]*s1);
    }
    // attention + out: 2048 elements each -> 2 per thread
    {
        int p = t % 32;
        float so0 = g_out[p]*rsqrtf(v_out[p]+EPSBN);
        float so1 = g_out[p+32]*rsqrtf(v_out[p+32]+EPSBN);
        #pragma unroll
        for (int half = 0; half < 2; half++) {
            int e = t + half*1024;
            int k = e / 32;
            d_wattn2[k*32+p] = make_float2(w_attn[k*64+p], w_attn[k*64+p+32]);
            d_wout2[k*32+p]  = make_float2(w_out[k*64+p]*so0, w_out[k*64+p+32]*so1);
        }
    }
    // shortcut: 1024
    {
        int k = t / 32, p = t % 32;
        float ss0 = g_sc[p]*rsqrtf(v_sc[p]+EPSBN);
        float ss1 = g_sc[p+32]*rsqrtf(v_sc[p+32]+EPSBN);
        d_wsc2[k*32+p] = make_float2(w_sc[k*64+p]*ss0, w_sc[k*64+p+32]*ss1);
    }
    // biases: 32 threads
    if (t < 32) {
        int p = t;
        float sr  = g_raw[p]*rsqrtf(v_raw[p]+EPSBN);
        d_braw[p] = (b_raw[p]-m_raw[p])*sr + be_raw[p];
        float s0 = g_nb[p]*rsqrtf(v_nb[p]+EPSBN);
        float s1 = g_nb[p+32]*rsqrtf(v_nb[p+32]+EPSBN);
        d_bnb2[p] = make_float2((b_nb[p]-m_nb[p])*s0+be_nb[p], (b_nb[p+32]-m_nb[p+32])*s1+be_nb[p+32]);
        float so0 = g_out[p]*rsqrtf(v_out[p]+EPSBN);
        float so1 = g_out[p+32]*rsqrtf(v_out[p+32]+EPSBN);
        d_bout2[p] = make_float2((b_out[p]-m_out[p])*so0+be_out[p], (b_out[p+32]-m_out[p+32])*so1+be_out[p+32]);
        float ss0 = g_sc[p]*rsqrtf(v_sc[p]+EPSBN);
        float ss1 = g_sc[p+32]*rsqrtf(v_sc[p+32]+EPSBN);
        d_bsc2[p] = make_float2((b_sc[p]-m_sc[p])*ss0+be_sc[p], (b_sc[p+32]-m_sc[p+32])*ss1+be_sc[p+32]);
    }
}

// ---- Kernel 1: G = feature @ W_nb_top'. One warp per point. ----
__global__ void __launch_bounds__(256) g_kernel(const float* __restrict__ feature)
{
    __shared__ float2 sw[32*32];
    for (int i = threadIdx.x; i < 1024; i += 256) sw[i] = d_wnbt2[i];
    __syncthreads();
    const int g = blockIdx.x*256 + threadIdx.x;
    const int pt = g >> 5, lane = g & 31;
    const float f = feature[pt*32 + lane];
    F2U acc; acc.f = make_float2(0.f, 0.f);
    #pragma unroll
    for (int k=0;k<32;k++){
        F2U w; w.f = sw[k*32+lane];
        ffma2(acc.u, packdup(__shfl_sync(0xffffffffu, f, k)), w.u);
    }
    d_G2[(size_t)pt*32 + lane] = acc.f;
}

// ---- Kernel 2: fused main. One warp/point; lane tile 4 rows x 4 pairs. ----
__global__ void __launch_bounds__(128) main_kernel(
    const float* __restrict__ feature,
    const float* __restrict__ raw,
    const int*   __restrict__ nbr,
    float*       __restrict__ outp)
{
    __shared__ float2 sh_wnbb[32*32];    // 8 KB
    __shared__ float2 sh_wattn[64*32];   // 16 KB
    __shared__ float  sh_wraw[10*32];    // 1.25 KB
    __shared__ float4 sh_st[4][256];     // 16 KB per-warp staging (rawT -> rmT -> hT)
    __shared__ float2 sh_pool[4][32];    // 1 KB

    const int tid = threadIdx.x;
    for (int i = tid; i < 32*32; i += 128) sh_wnbb[i]  = d_wnbb2[i];
    for (int i = tid; i < 64*32; i += 128) sh_wattn[i] = d_wattn2[i];
    for (int i = tid; i < 10*32; i += 128) sh_wraw[i]  = d_wraw[i];
    __syncthreads();

    const int lane = tid & 31, w = tid >> 5;
    const int mt = lane >> 3;      // row tile: rows 4mt..4mt+3
    const int ct = lane & 7;       // pair tile: pairs 4ct..4ct+3
    float4* const st   = sh_st[w];
    float*  const stf  = (float*)sh_st[w];
    float2* const pool = sh_pool[w];

    const int pt = blockIdx.x*4 + w;
    const int bbase = (pt >> 16) << 16;           // batch offset (N=65536)

    // neighbor indices (early)
    int idxv = 0;
    if (lane < 16) idxv = nbr[pt*16 + lane];

    // ---- raw_mlp as staged GEMM: rm = lrelu(raw @ W_raw' + b_raw') ----
    {
        // stage raw^T[k][m] into stf[k*16+m]
        #pragma unroll
        for (int i=0;i<5;i++){
            const int e = i*32 + lane;     // flat = m*10+k
            float v = raw[pt*160 + e];
            stf[(e % 10)*16 + (e / 10)] = v;
        }
        __syncwarp();

        float racc[4][4];
        {
            float4 b0 = *(const float4*)(d_braw + 4*ct);
            #pragma unroll
            for (int r=0;r<4;r++){
                racc[r][0]=b0.x; racc[r][1]=b0.y; racc[r][2]=b0.z; racc[r][3]=b0.w;
            }
        }
        #pragma unroll
        for (int k=0;k<10;k++){
            float4 a4 = st[k*4 + mt];                               // raw^T rows 4mt..4mt+3
            float4 b4 = *(const float4*)(sh_wraw + k*32 + 4*ct);    // cols 4ct..4ct+3
            float av[4] = {a4.x, a4.y, a4.z, a4.w};
            float bv[4] = {b4.x, b4.y, b4.z, b4.w};
            #pragma unroll
            for (int r=0;r<4;r++)
                #pragma unroll
                for (int i=0;i<4;i++) racc[r][i] = fmaf(av[r], bv[i], racc[r][i]);
        }
        __syncwarp();
        // stage rm^T: st[j*4+mt] = rows 4mt..4mt+3 of column j
        #pragma unroll
        for (int i=0;i<4;i++){
            st[(4*ct+i)*4 + mt] = make_float4(lrelu(racc[0][i]), lrelu(racc[1][i]),
                                              lrelu(racc[2][i]), lrelu(racc[3][i]));
        }
        __syncwarp();
    }

    // ---- R = raw_mlp @ W_nb_bot' + b_nb'  (K=32) ----
    F2U acc2[4][4];
    #pragma unroll
    for (int r=0;r<4;r++)
        #pragma unroll
        for (int i=0;i<4;i++) acc2[r][i].f = d_bnb2[4*ct + i];

    #pragma unroll 4
    for (int j=0;j<32;j++){
        float4 a4 = st[j*4 + mt];
        ulonglong2 b01 = *(const ulonglong2*)(sh_wnbb + j*32 + 4*ct);
        ulonglong2 b23 = *(const ulonglong2*)(sh_wnbb + j*32 + 4*ct + 2);
        float av[4] = {a4.x, a4.y, a4.z, a4.w};
        #pragma unroll
        for (int r=0;r<4;r++){
            unsigned long long ad = packdup(av[r]);
            ffma2(acc2[r][0].u, ad, b01.x); ffma2(acc2[r][1].u, ad, b01.y);
            ffma2(acc2[r][2].u, ad, b23.x); ffma2(acc2[r][3].u, ad, b23.y);
        }
    }

    // ---- gather G (L2-resident) directly into accumulators; h = lrelu(G + R) ----
    #pragma unroll
    for (int r=0;r<4;r++){
        int j = __shfl_sync(0xffffffffu, idxv, 4*mt + r);
        const float2* gp = d_G2 + ((size_t)(bbase + j)*32 + 4*ct);
        float4 lo = *(const float4*)gp;
        float4 hi = *(const float4*)(gp + 2);
        acc2[r][0].f = make_float2(lrelu(acc2[r][0].f.x + lo.x), lrelu(acc2[r][0].f.y + lo.y));
        acc2[r][1].f = make_float2(lrelu(acc2[r][1].f.x + lo.z), lrelu(acc2[r][1].f.y + lo.w));
        acc2[r][2].f = make_float2(lrelu(acc2[r][2].f.x + hi.x), lrelu(acc2[r][2].f.y + hi.y));
        acc2[r][3].f = make_float2(lrelu(acc2[r][3].f.x + hi.z), lrelu(acc2[r][3].f.y + hi.w));
    }

    // stage h^T over channels (x-half cols 0..31, y-half cols 32..63)
    __syncwarp();
    #pragma unroll
    for (int i=0;i<4;i++){
        st[(4*ct+i)*4 + mt]    = make_float4(acc2[0][i].f.x, acc2[1][i].f.x, acc2[2][i].f.x, acc2[3][i].f.x);
        st[(4*ct+i+32)*4 + mt] = make_float4(acc2[0][i].f.y, acc2[1][i].f.y, acc2[2][i].f.y, acc2[3][i].f.y);
    }
    __syncwarp();

    // ---- s = h @ w_attn  (K=64) ----  (acc2 regs are dead now)
    F2U s2[4][4];
    #pragma unroll
    for (int r=0;r<4;r++)
        #pragma unroll
        for (int i=0;i<4;i++) s2[r][i].f = make_float2(0.f, 0.f);

    #pragma unroll 4
    for (int k=0;k<64;k++){
        float4 a4 = st[k*4 + mt];
        ulonglong2 b01 = *(const ulonglong2*)(sh_wattn + k*32 + 4*ct);
        ulonglong2 b23 = *(const ulonglong2*)(sh_wattn + k*32 + 4*ct + 2);
        float av[4] = {a4.x, a4.y, a4.z, a4.w};
        #pragma unroll
        for (int r=0;r<4;r++){
            unsigned long long ad = packdup(av[r]);
            ffma2(s2[r][0].u, ad, b01.x); ffma2(s2[r][1].u, ad, b01.y);
            ffma2(s2[r][2].u, ad, b23.x); ffma2(s2[r][3].u, ad, b23.y);
        }
    }

    // ---- softmax over 16 rows + pooling (h re-read from shared) ----
    float px[4], py[4];
    #pragma unroll
    for (int i=0;i<4;i++){
        float4 hx = st[(4*ct+i)*4 + mt];      // h rows 4mt..4mt+3, channel 4ct+i
        float4 hy = st[(4*ct+i+32)*4 + mt];   // channel 4ct+i+32
        float hxa[4] = {hx.x, hx.y, hx.z, hx.w};
        float hya[4] = {hy.x, hy.y, hy.z, hy.w};

        float mx = fmaxf(fmaxf(s2[0][i].f.x, s2[1][i].f.x), fmaxf(s2[2][i].f.x, s2[3][i].f.x));
        float my = fmaxf(fmaxf(s2[0][i].f.y, s2[1][i].f.y), fmaxf(s2[2][i].f.y, s2[3][i].f.y));
        mx = fmaxf(mx, __shfl_xor_sync(0xffffffffu, mx, 8));
        mx = fmaxf(mx, __shfl_xor_sync(0xffffffffu, mx, 16));
        my = fmaxf(my, __shfl_xor_sync(0xffffffffu, my, 8));
        my = fmaxf(my, __shfl_xor_sync(0xffffffffu, my, 16));
        float sx = 0.f, sy = 0.f, pxx = 0.f, pyy = 0.f;
        #pragma unroll
        for (int r=0;r<4;r++){
            float ex = __expf(s2[r][i].f.x - mx);
            float ey = __expf(s2[r][i].f.y - my);
            sx += ex; sy += ey;
            pxx = fmaf(ex, hxa[r], pxx);
            pyy = fmaf(ey, hya[r], pyy);
        }
        sx += __shfl_xor_sync(0xffffffffu, sx, 8);  sx += __shfl_xor_sync(0xffffffffu, sx, 16);
        sy += __shfl_xor_sync(0xffffffffu, sy, 8);  sy += __shfl_xor_sync(0xffffffffu, sy, 16);
        pxx += __shfl_xor_sync(0xffffffffu, pxx, 8); pxx += __shfl_xor_sync(0xffffffffu, pxx, 16);
        pyy += __shfl_xor_sync(0xffffffffu, pyy, 8); pyy += __shfl_xor_sync(0xffffffffu, pyy, 16);
        px[i] = __fdividef(pxx, sx); py[i] = __fdividef(pyy, sy);
    }
    __syncwarp();
    if (mt == 0){
        #pragma unroll
        for (int i=0;i<4;i++) pool[4*ct+i] = make_float2(px[i], py[i]);
    }
    __syncwarp();

    // ---- out = pooled @ w_out' + b_out'; sc = feature @ w_sc' + b_sc' ----
    F2U oacc; oacc.f = d_bout2[lane];
    #pragma unroll 8
    for (int p=0;p<32;p++){
        float2 pv = pool[p];
        F2U w0; w0.f = d_wout2[p*32 + lane];
        F2U w1; w1.f = d_wout2[(p+32)*32 + lane];
        ffma2(oacc.u, packdup(pv.x), w0.u);
        ffma2(oacc.u, packdup(pv.y), w1.u);
    }

    F2U sacc; sacc.f = d_bsc2[lane];
    const float fv = feature[pt*32 + lane];
    #pragma unroll 8
    for (int k=0;k<32;k++){
        F2U wv; wv.f = d_wsc2[k*32 + lane];
        ffma2(sacc.u, packdup(__shfl_sync(0xffffffffu, fv, k)), wv.u);
    }

    outp[pt*64 + lane]      = lrelu(sacc.f.x + oacc.f.x);
    outp[pt*64 + lane + 32] = lrelu(sacc.f.y + oacc.f.y);
}

extern "C" void kernel_launch(void* const* d_in, const int* in_sizes, int n_in,
                              void* d_out, int out_size)
{
    const float* feature = (const float*)d_in[0];
    const float* raw     = (const float*)d_in[1];
    const int*   nbr     = (const int*)  d_in[2];

    fold_kernel<<<1, 1024>>>(
        (const float*)d_in[3],  (const float*)d_in[4],  (const float*)d_in[5],
        (const float*)d_in[6],  (const float*)d_in[7],  (const float*)d_in[8],
        (const float*)d_in[9],  (const float*)d_in[10], (const float*)d_in[11],
        (const float*)d_in[12], (const float*)d_in[13], (const float*)d_in[14],
        (const float*)d_in[15],
        (const float*)d_in[16], (const float*)d_in[17], (const float*)d_in[18],
        (const float*)d_in[19], (const float*)d_in[20], (const float*)d_in[21],
        (const float*)d_in[22], (const float*)d_in[23], (const float*)d_in[24],
        (const float*)d_in[25], (const float*)d_in[26], (const float*)d_in[27]);

    g_kernel<<<(NPTS*32)/256, 256>>>(feature);

    main_kernel<<<NPTS/4, 128>>>(feature, raw, nbr, (float*)d_out);
}

// round 9
// speedup vs baseline: 1.7960x; 1.7846x over previous
#include <cuda_runtime.h>
#include <cstdint>

#define NPTS   131072          // B*N = 2*65536
#define EPSBN  1e-5f

// ---- fragment-ordered tf32 weight tables + folded params (device globals) ----
__device__ __align__(16) uint4  d_fragRaw[2*4*32];   // raw mlp: K=16(pad of 10), N=32
__device__ __align__(16) uint4  d_fragR[4*8*32];     // W_nb bottom: K=32, N=64
__device__ __align__(16) uint4  d_fragS[8*8*32];     // w_attn: K=64, N=64
__device__ __align__(16) float  d_braw[32];
__device__ __align__(16) float  d_bnb[64];
__device__ __align__(16) float2 d_wnbt2[32*32];      // W_nb top (for G), pair (c, c+32)
__device__ __align__(16) float2 d_wout2[64*32];
__device__ __align__(16) float2 d_bout2[32];
__device__ __align__(16) float2 d_wsc2[32*32];
__device__ __align__(16) float2 d_bsc2[32];
__device__ __align__(16) float  d_G[(size_t)NPTS*64]; // G = feature @ W_nb_top' (~33.5MB, L2)

union F2U { float2 f; unsigned long long u; };
__device__ __forceinline__ unsigned long long packdup(float a){
    unsigned long long r; asm("mov.b64 %0, {%1, %1};" : "=l"(r) : "f"(a)); return r;
}
__device__ __forceinline__ void ffma2(unsigned long long& d, unsigned long long a, unsigned long long b){
    asm("fma.rn.f32x2 %0, %1, %2, %0;" : "+l"(d) : "l"(a), "l"(b));
}
__device__ __forceinline__ float lrelu(float x){ return fmaxf(x, 0.2f*x); }

__device__ __forceinline__ void split_tf32(float x, uint32_t& hi, uint32_t& lo){
    asm("cvt.rna.tf32.f32 %0, %1;" : "=r"(hi) : "f"(x));
    float l = x - __uint_as_float(hi);
    asm("cvt.rna.tf32.f32 %0, %1;" : "=r"(lo) : "f"(l));
}
__device__ __forceinline__ void mma_tf32(float* d, const uint32_t* a, uint32_t b0, uint32_t b1){
    asm volatile("mma.sync.aligned.m16n8k8.row.col.f32.tf32.tf32.f32 "
        "{%0,%1,%2,%3},{%4,%5,%6,%7},{%8,%9},{%0,%1,%2,%3};"
        : "+f"(d[0]),"+f"(d[1]),"+f"(d[2]),"+f"(d[3])
        : "r"(a[0]),"r"(a[1]),"r"(a[2]),"r"(a[3]),"r"(b0),"r"(b1));
}
__device__ __forceinline__ void mma3(float* d, const uint32_t* ah, const uint32_t* al, uint4 b){
    mma_tf32(d, ah, b.x, b.y);   // Ah*Bh
    mma_tf32(d, al, b.x, b.y);   // Al*Bh
    mma_tf32(d, ah, b.z, b.w);   // Ah*Bl
}

// ---- Kernel 0: fold BN into weights; build tf32 fragment tables. ----
__global__ void __launch_bounds__(1024) fold_kernel(
    const float* w_raw, const float* b_raw, const float* g_raw, const float* be_raw,
    const float* m_raw, const float* v_raw,
    const float* w_nb,  const float* b_nb,  const float* g_nb,  const float* be_nb,
    const float* m_nb,  const float* v_nb,  const float* w_attn,
    const float* w_out, const float* b_out, const float* g_out, const float* be_out,
    const float* m_out, const float* v_out,
    const float* w_sc,  const float* b_sc,  const float* g_sc,  const float* be_sc,
    const float* m_sc,  const float* v_sc)
{
    const int t0 = threadIdx.x;

    // fragRaw: 256 entries. B[k][n] = w_raw[k][n]*s_raw(n), k<10 else 0 (K padded to 16)
    if (t0 < 256){
        int lane = t0 & 31, nt = (t0>>5)&3, kc = t0>>7;
        int gg = lane>>2, tt = lane&3, n = nt*8+gg;
        float sn = g_raw[n]*rsqrtf(v_raw[n]+EPSBN);
        int k0 = kc*8+tt, k1 = k0+4;
        float w0 = (k0<10)? w_raw[k0*32+n]*sn : 0.f;
        float w1 = (k1<10)? w_raw[k1*32+n]*sn : 0.f;
        uint32_t h0,l0,h1,l1; split_tf32(w0,h0,l0); split_tf32(w1,h1,l1);
        d_fragRaw[t0] = make_uint4(h0,h1,l0,l1);
    }
    // fragR: 1024 entries. B[k][n] = w_nb[32+k][n]*s_nb(n)
    {
        int idx = t0;
        int lane = idx & 31, nt = (idx>>5)&7, kc = idx>>8;
        int gg = lane>>2, tt = lane&3, n = nt*8+gg;
        float sn = g_nb[n]*rsqrtf(v_nb[n]+EPSBN);
        int k0 = kc*8+tt, k1 = k0+4;
        float w0 = w_nb[(32+k0)*64+n]*sn;
        float w1 = w_nb[(32+k1)*64+n]*sn;
        uint32_t h0,l0,h1,l1; split_tf32(w0,h0,l0); split_tf32(w1,h1,l1);
        d_fragR[idx] = make_uint4(h0,h1,l0,l1);
    }
    // fragS: 2048 entries (2 per thread). B[k][n] = w_attn[k][n]
    #pragma unroll
    for (int half = 0; half < 2; half++){
        int idx = t0 + half*1024;
        int lane = idx & 31, nt = (idx>>5)&7, kc = idx>>8;
        int gg = lane>>2, tt = lane&3, n = nt*8+gg;
        int k0 = kc*8+tt, k1 = k0+4;
        float w0 = w_attn[k0*64+n];
        float w1 = w_attn[k1*64+n];
        uint32_t h0,l0,h1,l1; split_tf32(w0,h0,l0); split_tf32(w1,h1,l1);
        d_fragS[idx] = make_uint4(h0,h1,l0,l1);
    }
    // W_nb top (paired) for g_kernel: 1024 entries
    {
        int k = t0/32, p = t0%32;
        float s0 = g_nb[p]*rsqrtf(v_nb[p]+EPSBN);
        float s1 = g_nb[p+32]*rsqrtf(v_nb[p+32]+EPSBN);
        d_wnbt2[k*32+p] = make_float2(w_nb[k*64+p]*s0, w_nb[k*64+p+32]*s1);
    }
    // w_out (2048: 2 per thread), w_sc (1024)
    {
        int p = t0 % 32;
        float so0 = g_out[p]*rsqrtf(v_out[p]+EPSBN);
        float so1 = g_out[p+32]*rsqrtf(v_out[p+32]+EPSBN);
        #pragma unroll
        for (int half = 0; half < 2; half++){
            int e = t0 + half*1024;
            int k = e / 32;
            d_wout2[k*32+p] = make_float2(w_out[k*64+p]*so0, w_out[k*64+p+32]*so1);
        }
        int k = t0 / 32;
        float ss0 = g_sc[p]*rsqrtf(v_sc[p]+EPSBN);
        float ss1 = g_sc[p+32]*rsqrtf(v_sc[p+32]+EPSBN);
        d_wsc2[k*32+p] = make_float2(w_sc[k*64+p]*ss0, w_sc[k*64+p+32]*ss1);
    }
    // biases
    if (t0 < 64){
        int p = t0;
        float s = g_nb[p]*rsqrtf(v_nb[p]+EPSBN);
        d_bnb[p] = (b_nb[p]-m_nb[p])*s + be_nb[p];
    }
    if (t0 < 32){
        int p = t0;
        float sr = g_raw[p]*rsqrtf(v_raw[p]+EPSBN);
        d_braw[p] = (b_raw[p]-m_raw[p])*sr + be_raw[p];
        float so0 = g_out[p]*rsqrtf(v_out[p]+EPSBN);
        float so1 = g_out[p+32]*rsqrtf(v_out[p+32]+EPSBN);
        d_bout2[p] = make_float2((b_out[p]-m_out[p])*so0+be_out[p],
                                 (b_out[p+32]-m_out[p+32])*so1+be_out[p+32]);
        float ss0 = g_sc[p]*rsqrtf(v_sc[p]+EPSBN);
        float ss1 = g_sc[p+32]*rsqrtf(v_sc[p+32]+EPSBN);
        d_bsc2[p] = make_float2((b_sc[p]-m_sc[p])*ss0+be_sc[p],
                                (b_sc[p+32]-m_sc[p+32])*ss1+be_sc[p+32]);
    }
}

// ---- Kernel 1: G = feature @ W_nb_top' (natural [pt][64] layout). ----
__global__ void __launch_bounds__(256) g_kernel(const float* __restrict__ feature)
{
    __shared__ float2 sw[32*32];
    for (int i = threadIdx.x; i < 1024; i += 256) sw[i] = d_wnbt2[i];
    __syncthreads();
    const int gidx = blockIdx.x*256 + threadIdx.x;
    const int pt = gidx >> 5, lane = gidx & 31;
    const float f = feature[pt*32 + lane];
    F2U acc; acc.f = make_float2(0.f, 0.f);
    #pragma unroll
    for (int k=0;k<32;k++){
        F2U w; w.f = sw[k*32+lane];
        ffma2(acc.u, packdup(__shfl_sync(0xffffffffu, f, k)), w.u);
    }
    d_G[(size_t)pt*64 + lane]      = acc.f.x;
    d_G[(size_t)pt*64 + lane + 32] = acc.f.y;
}

// ---- Kernel 2: fused main. One warp/point; tensor-core (tf32 3-split) GEMMs. ----
// mma m16n8k8 lane roles: g = lane>>2 (0..7), t = lane&3 (0..3).
// A frag: a0=(g,t) a1=(g+8,t) a2=(g,t+4) a3=(g+8,t+4)
// B frag: b0=B[t][g] b1=B[t+4][g]  (col-major 8x8)
// D frag: c0=(g,2t) c1=(g,2t+1) c2=(g+8,2t) c3=(g+8,2t+1)
__global__ void __launch_bounds__(256) main_kernel(
    const float* __restrict__ feature,
    const float* __restrict__ raw,
    const int*   __restrict__ nbr,
    float*       __restrict__ outp)
{
    __shared__ __align__(16) float stg[8][1092];   // per-warp staging (rawS/rmS/hS)
    __shared__ __align__(16) float poolS[8][64];

    const int tid = threadIdx.x, lane = tid & 31, w = tid >> 5;
    const int g = lane >> 2, t = lane & 3;
    float* const st   = stg[w];
    float* const pool = poolS[w];

    const int pt = blockIdx.x*8 + w;
    const int bbase = (pt >> 16) << 16;     // batch offset (N=65536)

    int idxv = 0;
    if (lane < 16) idxv = nbr[pt*16 + lane];
    const int jr0 = __shfl_sync(0xffffffffu, idxv, g);
    const int jr1 = __shfl_sync(0xffffffffu, idxv, g+8);

    // ---- stage rawS[m][k], pad 20 (conflict-free frag loads); zero-pad k=10..15 ----
    #pragma unroll
    for (int i=0;i<5;i++){
        int e = i*32 + lane;                     // m = e/10, k = e%10
        st[(e/10)*20 + (e%10)] = raw[pt*160 + e];
    }
    #pragma unroll
    for (int i=0;i<3;i++){
        int e = i*32 + lane;                     // 0..95 : m=e/6, k=10+e%6
        st[(e/6)*20 + 10 + (e%6)] = 0.f;
    }
    __syncwarp();

    // ---- raw mlp: rmD(16x32) = rawS(16x16) @ WrawFrag + braw ----
    float rmD[4][4];
    #pragma unroll
    for (int nt=0;nt<4;nt++){
        float2 b = *(const float2*)&d_braw[nt*8 + 2*t];
        rmD[nt][0]=b.x; rmD[nt][1]=b.y; rmD[nt][2]=b.x; rmD[nt][3]=b.y;
    }
    #pragma unroll
    for (int kc=0;kc<2;kc++){
        float af[4] = { st[g*20+kc*8+t],   st[(g+8)*20+kc*8+t],
                        st[g*20+kc*8+t+4], st[(g+8)*20+kc*8+t+4] };
        uint32_t ah[4], al[4];
        #pragma unroll
        for (int i=0;i<4;i++) split_tf32(af[i], ah[i], al[i]);
        #pragma unroll
        for (int nt=0;nt<4;nt++)
            mma3(rmD[nt], ah, al, d_fragRaw[(kc*4+nt)*32 + lane]);
    }
    __syncwarp();
    // stage rm (lrelu) as rmS[m][c], pad 36
    #pragma unroll
    for (int nt=0;nt<4;nt++){
        *(float2*)&st[g*36     + nt*8 + 2*t] = make_float2(lrelu(rmD[nt][0]), lrelu(rmD[nt][1]));
        *(float2*)&st[(g+8)*36 + nt*8 + 2*t] = make_float2(lrelu(rmD[nt][2]), lrelu(rmD[nt][3]));
    }
    __syncwarp();

    // ---- R-GEMM: hD(16x64) = rm(16x32) @ W_nbb + bnb ----
    float hD[8][4];
    #pragma unroll
    for (int nt=0;nt<8;nt++){
        float2 b = *(const float2*)&d_bnb[nt*8 + 2*t];
        hD[nt][0]=b.x; hD[nt][1]=b.y; hD[nt][2]=b.x; hD[nt][3]=b.y;
    }
    #pragma unroll
    for (int kc=0;kc<4;kc++){
        float af[4] = { st[g*36+kc*8+t],   st[(g+8)*36+kc*8+t],
                        st[g*36+kc*8+t+4], st[(g+8)*36+kc*8+t+4] };
        uint32_t ah[4], al[4];
        #pragma unroll
        for (int i=0;i<4;i++) split_tf32(af[i], ah[i], al[i]);
        #pragma unroll
        for (int nt=0;nt<8;nt++)
            mma3(hD[nt], ah, al, d_fragR[(kc*8+nt)*32 + lane]);
    }

    // ---- gather G (L2) and h = lrelu(G + hD); keep hv in D-frag regs ----
    float hv[8][4];
    const float* G0 = d_G + (size_t)(bbase + jr0)*64;
    const float* G1 = d_G + (size_t)(bbase + jr1)*64;
    #pragma unroll
    for (int nt=0;nt<8;nt++){
        float2 ga = *(const float2*)&G0[nt*8 + 2*t];
        float2 gb = *(const float2*)&G1[nt*8 + 2*t];
        hv[nt][0] = lrelu(hD[nt][0] + ga.x);
        hv[nt][1] = lrelu(hD[nt][1] + ga.y);
        hv[nt][2] = lrelu(hD[nt][2] + gb.x);
        hv[nt][3] = lrelu(hD[nt][3] + gb.y);
    }
    __syncwarp();
    // stage hS[m][c], pad 68 (conflict-free A-frag loads)
    #pragma unroll
    for (int nt=0;nt<8;nt++){
        *(float2*)&st[g*68     + nt*8 + 2*t] = make_float2(hv[nt][0], hv[nt][1]);
        *(float2*)&st[(g+8)*68 + nt*8 + 2*t] = make_float2(hv[nt][2], hv[nt][3]);
    }
    __syncwarp();

    // ---- s-GEMM: sD(16x64) = h(16x64) @ w_attn ----
    float sD[8][4];
    #pragma unroll
    for (int nt=0;nt<8;nt++){ sD[nt][0]=0.f; sD[nt][1]=0.f; sD[nt][2]=0.f; sD[nt][3]=0.f; }
    #pragma unroll
    for (int kc=0;kc<8;kc++){
        float af[4] = { st[g*68+kc*8+t],   st[(g+8)*68+kc*8+t],
                        st[g*68+kc*8+t+4], st[(g+8)*68+kc*8+t+4] };
        uint32_t ah[4], al[4];
        #pragma unroll
        for (int i=0;i<4;i++) split_tf32(af[i], ah[i], al[i]);
        #pragma unroll
        for (int nt=0;nt<8;nt++)
            mma3(sD[nt], ah, al, d_fragS[(kc*8+nt)*32 + lane]);
    }

    // ---- softmax over 16 neighbors (no max shift: |s| small) + attention pooling ----
    #pragma unroll
    for (int nt=0;nt<8;nt++){
        float e0=__expf(sD[nt][0]), e1=__expf(sD[nt][1]);
        float e2=__expf(sD[nt][2]), e3=__expf(sD[nt][3]);
        float den0 = e0+e2, num0 = fmaf(e0, hv[nt][0], e2*hv[nt][2]);
        float den1 = e1+e3, num1 = fmaf(e1, hv[nt][1], e3*hv[nt][3]);
        #pragma unroll
        for (int m=4;m<=16;m<<=1){
            den0 += __shfl_xor_sync(0xffffffffu, den0, m);
            num0 += __shfl_xor_sync(0xffffffffu, num0, m);
            den1 += __shfl_xor_sync(0xffffffffu, den1, m);
            num1 += __shfl_xor_sync(0xffffffffu, num1, m);
        }
        if (g == 0)
            *(float2*)&pool[nt*8 + 2*t] =
                make_float2(__fdividef(num0,den0), __fdividef(num1,den1));
    }
    __syncwarp();

    // ---- out = pooled @ w_out' + b_out'; sc = feature @ w_sc' + b_sc' ----
    F2U oacc; oacc.f = d_bout2[lane];
    #pragma unroll 8
    for (int p=0;p<64;p++){
        F2U wv; wv.f = d_wout2[p*32 + lane];
        ffma2(oacc.u, packdup(pool[p]), wv.u);
    }
    F2U sacc; sacc.f = d_bsc2[lane];
    const float fv = feature[pt*32 + lane];
    #pragma unroll 8
    for (int k=0;k<32;k++){
        F2U wv; wv.f = d_wsc2[k*32 + lane];
        ffma2(sacc.u, packdup(__shfl_sync(0xffffffffu, fv, k)), wv.u);
    }

    outp[pt*64 + lane]      = lrelu(sacc.f.x + oacc.f.x);
    outp[pt*64 + lane + 32] = lrelu(sacc.f.y + oacc.f.y);
}

extern "C" void kernel_launch(void* const* d_in, const int* in_sizes, int n_in,
                              void* d_out, int out_size)
{
    const float* feature = (const float*)d_in[0];
    const float* raw     = (const float*)d_in[1];
    const int*   nbr     = (const int*)  d_in[2];

    fold_kernel<<<1, 1024>>>(
        (const float*)d_in[3],  (const float*)d_in[4],  (const float*)d_in[5],
        (const float*)d_in[6],  (const float*)d_in[7],  (const float*)d_in[8],
        (const float*)d_in[9],  (const float*)d_in[10], (const float*)d_in[11],
        (const float*)d_in[12], (const float*)d_in[13], (const float*)d_in[14],
        (const float*)d_in[15],
        (const float*)d_in[16], (const float*)d_in[17], (const float*)d_in[18],
        (const float*)d_in[19], (const float*)d_in[20], (const float*)d_in[21],
        (const float*)d_in[22], (const float*)d_in[23], (const float*)d_in[24],
        (const float*)d_in[25], (const float*)d_in[26], (const float*)d_in[27]);

    g_kernel<<<(NPTS*32)/256, 256>>>(feature);

    main_kernel<<<NPTS/8, 256>>>(feature, raw, nbr, (float*)d_out);
}

// round 10
// speedup vs baseline: 2.5810x; 1.4371x over previous
#include <cuda_runtime.h>
#include <cstdint>

#define NPTS   131072          // B*N = 2*65536
#define EPSBN  1e-5f

// ---- fragment-ordered bf16 weight tables + folded params (device globals) ----
__device__ __align__(16) uint4  d_fragRaw[4*32];     // raw mlp: K=16(pad of 10), N=32 (4 nt)
__device__ __align__(16) uint4  d_fragR[16*32];      // W_nb bottom: K=32 (2 kc), N=64 (8 nt)
__device__ __align__(16) uint4  d_fragS[32*32];      // w_attn: K=64 (4 kc), N=64 (8 nt)
__device__ __align__(16) float  d_braw[32];
__device__ __align__(16) float  d_bnb[64];
__device__ __align__(16) float2 d_wnbt2[32*32];      // W_nb top (for G), pair (c, c+32)
__device__ __align__(16) float2 d_wout2[64*32];
__device__ __align__(16) float2 d_bout2[32];
__device__ __align__(16) float2 d_wsc2[32*32];
__device__ __align__(16) float2 d_bsc2[32];
__device__ __align__(16) float  d_G[(size_t)NPTS*64]; // G = feature @ W_nb_top' (~33.5MB, L2)

union F2U { float2 f; unsigned long long u; };
__device__ __forceinline__ unsigned long long packdup(float a){
    unsigned long long r; asm("mov.b64 %0, {%1, %1};" : "=l"(r) : "f"(a)); return r;
}
__device__ __forceinline__ void ffma2(unsigned long long& d, unsigned long long a, unsigned long long b){
    asm("fma.rn.f32x2 %0, %1, %2, %0;" : "+l"(d) : "l"(a), "l"(b));
}
__device__ __forceinline__ float lrelu(float x){ return fmaxf(x, 0.2f*x); }

// pack two fp32 into bf16x2: low half = lo, high half = hi
__device__ __forceinline__ uint32_t pack_bf16x2(float lo, float hi){
    uint32_t r; asm("cvt.rn.bf16x2.f32 %0, %1, %2;" : "=r"(r) : "f"(hi), "f"(lo)); return r;
}
// split fp32 pair into bf16 hi + bf16 residual (3-split precision: ~2^-17)
__device__ __forceinline__ void split_pair(float x0, float x1, uint32_t& ah, uint32_t& al){
    ah = pack_bf16x2(x0, x1);
    float h0 = __uint_as_float(ah << 16);
    float h1 = __uint_as_float(ah & 0xFFFF0000u);
    al = pack_bf16x2(x0 - h0, x1 - h1);
}
__device__ __forceinline__ void mma_bf16(float* d, const uint32_t* a, uint32_t b0, uint32_t b1){
    asm volatile("mma.sync.aligned.m16n8k16.row.col.f32.bf16.bf16.f32 "
        "{%0,%1,%2,%3},{%4,%5,%6,%7},{%8,%9},{%0,%1,%2,%3};"
        : "+f"(d[0]),"+f"(d[1]),"+f"(d[2]),"+f"(d[3])
        : "r"(a[0]),"r"(a[1]),"r"(a[2]),"r"(a[3]),"r"(b0),"r"(b1));
}
__device__ __forceinline__ void mma3(float* d, const uint32_t* ah, const uint32_t* al, uint4 b){
    mma_bf16(d, ah, b.x, b.y);   // Ah*Bh
    mma_bf16(d, al, b.x, b.y);   // Al*Bh
    mma_bf16(d, ah, b.z, b.w);   // Ah*Bl
}
// build A-frags (ah/al) from two adjacent fp32 D-tiles (register chaining)
__device__ __forceinline__ void dfrags_to_afrags(const float* dA, const float* dB,
                                                 uint32_t* ah, uint32_t* al){
    split_pair(dA[0], dA[1], ah[0], al[0]);   // row g,   k 2t,2t+1
    split_pair(dA[2], dA[3], ah[1], al[1]);   // row g+8, k 2t,2t+1
    split_pair(dB[0], dB[1], ah[2], al[2]);   // row g,   k 2t+8,2t+9
    split_pair(dB[2], dB[3], ah[3], al[3]);   // row g+8, k 2t+8,2t+9
}

// ---- Kernel 0: fold BN into weights; build bf16 fragment tables. ----
__global__ void __launch_bounds__(1024) fold_kernel(
    const float* w_raw, const float* b_raw, const float* g_raw, const float* be_raw,
    const float* m_raw, const float* v_raw,
    const float* w_nb,  const float* b_nb,  const float* g_nb,  const float* be_nb,
    const float* m_nb,  const float* v_nb,  const float* w_attn,
    const float* w_out, const float* b_out, const float* g_out, const float* be_out,
    const float* m_out, const float* v_out,
    const float* w_sc,  const float* b_sc,  const float* g_sc,  const float* be_sc,
    const float* m_sc,  const float* v_sc)
{
    const int t0 = threadIdx.x;
    const int lane = t0 & 31, gg = lane >> 2, tt = lane & 3;

    // fragRaw: 128 entries (nt 0..3). K rows 2t,2t+1 (b0) and 2t+8,2t+9 (b1); k>=10 -> 0
    if (t0 < 128){
        int nt = t0 >> 5, n = nt*8 + gg;
        float sn = g_raw[n]*rsqrtf(v_raw[n]+EPSBN);
        int k0 = 2*tt, k2 = 2*tt + 8;
        float w0 = w_raw[k0*32+n]*sn;
        float w1 = w_raw[(k0+1)*32+n]*sn;
        float w2 = (k2   < 10) ? w_raw[k2*32+n]*sn     : 0.f;
        float w3 = (k2+1 < 10) ? w_raw[(k2+1)*32+n]*sn : 0.f;
        uint32_t h0,l0,h1,l1; split_pair(w0,w1,h0,l0); split_pair(w2,w3,h1,l1);
        d_fragRaw[t0] = make_uint4(h0,h1,l0,l1);
    }
    // fragR: 512 entries (entry = kc*8+nt)
    if (t0 < 512){
        int entry = t0 >> 5, nt = entry & 7, kc = entry >> 3, n = nt*8 + gg;
        float sn = g_nb[n]*rsqrtf(v_nb[n]+EPSBN);
        int k0 = kc*16 + 2*tt;
        float w0 = w_nb[(32+k0)*64+n]*sn,   w1 = w_nb[(32+k0+1)*64+n]*sn;
        float w2 = w_nb[(32+k0+8)*64+n]*sn, w3 = w_nb[(32+k0+9)*64+n]*sn;
        uint32_t h0,l0,h1,l1; split_pair(w0,w1,h0,l0); split_pair(w2,w3,h1,l1);
        d_fragR[t0] = make_uint4(h0,h1,l0,l1);
    }
    // fragS: 1024 entries (entry = kc*8+nt, kc 0..3)
    {
        int entry = t0 >> 5, nt = entry & 7, kc = entry >> 3, n = nt*8 + gg;
        int k0 = kc*16 + 2*tt;
        float w0 = w_attn[k0*64+n],     w1 = w_attn[(k0+1)*64+n];
        float w2 = w_attn[(k0+8)*64+n], w3 = w_attn[(k0+9)*64+n];
        uint32_t h0,l0,h1,l1; split_pair(w0,w1,h0,l0); split_pair(w2,w3,h1,l1);
        d_fragS[t0] = make_uint4(h0,h1,l0,l1);
    }
    // W_nb top (paired) for g_kernel: 1024 entries
    {
        int k = t0/32, p = t0%32;
        float s0 = g_nb[p]*rsqrtf(v_nb[p]+EPSBN);
        float s1 = g_nb[p+32]*rsqrtf(v_nb[p+32]+EPSBN);
        d_wnbt2[k*32+p] = make_float2(w_nb[k*64+p]*s0, w_nb[k*64+p+32]*s1);
    }
    // w_out (2048: 2/thread), w_sc (1024)
    {
        int p = t0 % 32;
        float so0 = g_out[p]*rsqrtf(v_out[p]+EPSBN);
        float so1 = g_out[p+32]*rsqrtf(v_out[p+32]+EPSBN);
        #pragma unroll
        for (int half = 0; half < 2; half++){
            int e = t0 + half*1024;
            int k = e / 32;
            d_wout2[k*32+p] = make_float2(w_out[k*64+p]*so0, w_out[k*64+p+32]*so1);
        }
        int k = t0 / 32;
        float ss0 = g_sc[p]*rsqrtf(v_sc[p]+EPSBN);
        float ss1 = g_sc[p+32]*rsqrtf(v_sc[p+32]+EPSBN);
        d_wsc2[k*32+p] = make_float2(w_sc[k*64+p]*ss0, w_sc[k*64+p+32]*ss1);
    }
    // biases
    if (t0 < 64){
        int p = t0;
        float s = g_nb[p]*rsqrtf(v_nb[p]+EPSBN);
        d_bnb[p] = (b_nb[p]-m_nb[p])*s + be_nb[p];
    }
    if (t0 < 32){
        int p = t0;
        float sr = g_raw[p]*rsqrtf(v_raw[p]+EPSBN);
        d_braw[p] = (b_raw[p]-m_raw[p])*sr + be_raw[p];
        float so0 = g_out[p]*rsqrtf(v_out[p]+EPSBN);
        float so1 = g_out[p+32]*rsqrtf(v_out[p+32]+EPSBN);
        d_bout2[p] = make_float2((b_out[p]-m_out[p])*so0+be_out[p],
                                 (b_out[p+32]-m_out[p+32])*so1+be_out[p+32]);
        float ss0 = g_sc[p]*rsqrtf(v_sc[p]+EPSBN);
        float ss1 = g_sc[p+32]*rsqrtf(v_sc[p+32]+EPSBN);
        d_bsc2[p] = make_float2((b_sc[p]-m_sc[p])*ss0+be_sc[p],
                                (b_sc[p+32]-m_sc[p+32])*ss1+be_sc[p+32]);
    }
}

// ---- Kernel 1: G = feature @ W_nb_top' (natural [pt][64] layout). ----
__global__ void __launch_bounds__(256) g_kernel(const float* __restrict__ feature)
{
    __shared__ float2 sw[32*32];
    for (int i = threadIdx.x; i < 1024; i += 256) sw[i] = d_wnbt2[i];
    __syncthreads();
    const int gidx = blockIdx.x*256 + threadIdx.x;
    const int pt = gidx >> 5, lane = gidx & 31;
    const float f = feature[pt*32 + lane];
    F2U acc; acc.f = make_float2(0.f, 0.f);
    #pragma unroll
    for (int k=0;k<32;k++){
        F2U wv; wv.f = sw[k*32+lane];
        ffma2(acc.u, packdup(__shfl_sync(0xffffffffu, f, k)), wv.u);
    }
    d_G[(size_t)pt*64 + lane]      = acc.f.x;
    d_G[(size_t)pt*64 + lane + 32] = acc.f.y;
}

// ---- Kernel 2: fused main. One warp/point; bf16 3-split m16n8k16 GEMM chain. ----
// mma lane roles: g = lane>>2 (0..7), t = lane&3 (0..3).
// D frag: c0=(g,2t) c1=(g,2t+1) c2=(g+8,2t) c3=(g+8,2t+1)
// A frag (k16): a0=(g,2t..2t+1) a1=(g+8,2t..) a2=(g,2t+8..) a3=(g+8,2t+8..)
//  -> A-frags of the next GEMM come straight from two adjacent D-tiles (no smem).
__global__ void __launch_bounds__(256) main_kernel(
    const float* __restrict__ feature,
    const float* __restrict__ raw,
    const int*   __restrict__ nbr,
    float*       __restrict__ outp)
{
    __shared__ __align__(16) float poolS[8][64];

    const int tid = threadIdx.x, lane = tid & 31, w = tid >> 5;
    const int g = lane >> 2, t = lane & 3;
    float* const pool = poolS[w];

    const int pt = blockIdx.x*8 + w;
    const int bbase = (pt >> 16) << 16;     // batch offset (N=65536)

    int idxv = 0;
    if (lane < 16) idxv = nbr[pt*16 + lane];
    const int jr0 = __shfl_sync(0xffffffffu, idxv, g);
    const int jr1 = __shfl_sync(0xffffffffu, idxv, g+8);

    // ---- raw A-frags straight from gmem (row m = 5 float2 of k-pairs) ----
    const float2* raw2 = (const float2*)raw + (size_t)pt*80;
    uint32_t ah[4], al[4];
    {
        float2 p0 = raw2[g*5 + t];
        float2 p1 = raw2[(g+8)*5 + t];
        float2 p2 = (t==0) ? raw2[g*5 + 4]     : make_float2(0.f,0.f);
        float2 p3 = (t==0) ? raw2[(g+8)*5 + 4] : make_float2(0.f,0.f);
        split_pair(p0.x, p0.y, ah[0], al[0]);
        split_pair(p1.x, p1.y, ah[1], al[1]);
        split_pair(p2.x, p2.y, ah[2], al[2]);
        split_pair(p3.x, p3.y, ah[3], al[3]);
    }

    // ---- raw mlp: rmD(16x32) = raw(16x16) @ Wraw + braw; lrelu in place ----
    float rmD[4][4];
    #pragma unroll
    for (int nt=0;nt<4;nt++){
        float2 b = *(const float2*)&d_braw[nt*8 + 2*t];
        rmD[nt][0]=b.x; rmD[nt][1]=b.y; rmD[nt][2]=b.x; rmD[nt][3]=b.y;
    }
    #pragma unroll
    for (int nt=0;nt<4;nt++)
        mma3(rmD[nt], ah, al, d_fragRaw[nt*32 + lane]);
    #pragma unroll
    for (int nt=0;nt<4;nt++)
        #pragma unroll
        for (int i=0;i<4;i++) rmD[nt][i] = lrelu(rmD[nt][i]);

    // ---- R-GEMM: hv(16x64) = rm(16x32) @ W_nbb + bnb  (A from rmD tiles) ----
    float hv[8][4];
    #pragma unroll
    for (int nt=0;nt<8;nt++){
        float2 b = *(const float2*)&d_bnb[nt*8 + 2*t];
        hv[nt][0]=b.x; hv[nt][1]=b.y; hv[nt][2]=b.x; hv[nt][3]=b.y;
    }
    #pragma unroll
    for (int kc=0;kc<2;kc++){
        dfrags_to_afrags(rmD[2*kc], rmD[2*kc+1], ah, al);
        #pragma unroll
        for (int nt=0;nt<8;nt++)
            mma3(hv[nt], ah, al, d_fragR[(kc*8+nt)*32 + lane]);
    }

    // ---- gather G (L2) and h = lrelu(G + hv), in place ----
    {
        const float* G0 = d_G + (size_t)(bbase + jr0)*64;
        const float* G1 = d_G + (size_t)(bbase + jr1)*64;
        #pragma unroll
        for (int nt=0;nt<8;nt++){
            float2 ga = *(const float2*)&G0[nt*8 + 2*t];
            float2 gb = *(const float2*)&G1[nt*8 + 2*t];
            hv[nt][0] = lrelu(hv[nt][0] + ga.x);
            hv[nt][1] = lrelu(hv[nt][1] + ga.y);
            hv[nt][2] = lrelu(hv[nt][2] + gb.x);
            hv[nt][3] = lrelu(hv[nt][3] + gb.y);
        }
    }

    // ---- s-GEMM: sD(16x64) = h(16x64) @ w_attn  (A from hv tiles) ----
    float sD[8][4];
    #pragma unroll
    for (int nt=0;nt<8;nt++){ sD[nt][0]=0.f; sD[nt][1]=0.f; sD[nt][2]=0.f; sD[nt][3]=0.f; }
    #pragma unroll 1
    for (int kc=0;kc<4;kc++){
        dfrags_to_afrags(hv[2*kc], hv[2*kc+1], ah, al);
        #pragma unroll
        for (int nt=0;nt<8;nt++)
            mma3(sD[nt], ah, al, d_fragS[(kc*8+nt)*32 + lane]);
    }

    // ---- softmax over 16 neighbors (no max shift: |s| small) + attention pooling ----
    #pragma unroll
    for (int nt=0;nt<8;nt++){
        float e0=__expf(sD[nt][0]), e1=__expf(sD[nt][1]);
        float e2=__expf(sD[nt][2]), e3=__expf(sD[nt][3]);
        float den0 = e0+e2, num0 = fmaf(e0, hv[nt][0], e2*hv[nt][2]);
        float den1 = e1+e3, num1 = fmaf(e1, hv[nt][1], e3*hv[nt][3]);
        #pragma unroll
        for (int m=4;m<=16;m<<=1){
            den0 += __shfl_xor_sync(0xffffffffu, den0, m);
            num0 += __shfl_xor_sync(0xffffffffu, num0, m);
            den1 += __shfl_xor_sync(0xffffffffu, den1, m);
            num1 += __shfl_xor_sync(0xffffffffu, num1, m);
        }
        if (g == 0)
            *(float2*)&pool[nt*8 + 2*t] =
                make_float2(__fdividef(num0,den0), __fdividef(num1,den1));
    }
    __syncwarp();

    // ---- out = pooled @ w_out' + b_out'; sc = feature @ w_sc' + b_sc' ----
    F2U oacc; oacc.f = d_bout2[lane];
    #pragma unroll 8
    for (int p=0;p<64;p++){
        F2U wv; wv.f = d_wout2[p*32 + lane];
        ffma2(oacc.u, packdup(pool[p]), wv.u);
    }
    F2U sacc; sacc.f = d_bsc2[lane];
    const float fv = feature[pt*32 + lane];
    #pragma unroll 8
    for (int k=0;k<32;k++){
        F2U wv; wv.f = d_wsc2[k*32 + lane];
        ffma2(sacc.u, packdup(__shfl_sync(0xffffffffu, fv, k)), wv.u);
    }

    outp[pt*64 + lane]      = lrelu(sacc.f.x + oacc.f.x);
    outp[pt*64 + lane + 32] = lrelu(sacc.f.y + oacc.f.y);
}

extern "C" void kernel_launch(void* const* d_in, const int* in_sizes, int n_in,
                              void* d_out, int out_size)
{
    const float* feature = (const float*)d_in[0];
    const float* raw     = (const float*)d_in[1];
    const int*   nbr     = (const int*)  d_in[2];

    fold_kernel<<<1, 1024>>>(
        (const float*)d_in[3],  (const float*)d_in[4],  (const float*)d_in[5],
        (const float*)d_in[6],  (const float*)d_in[7],  (const float*)d_in[8],
        (const float*)d_in[9],  (const float*)d_in[10], (const float*)d_in[11],
        (const float*)d_in[12], (const float*)d_in[13], (const float*)d_in[14],
        (const float*)d_in[15],
        (const float*)d_in[16], (const float*)d_in[17], (const float*)d_in[18],
        (const float*)d_in[19], (const float*)d_in[20], (const float*)d_in[21],
        (const float*)d_in[22], (const float*)d_in[23], (const float*)d_in[24],
        (const float*)d_in[25], (const float*)d_in[26], (const float*)d_in[27]);

    g_kernel<<<(NPTS*32)/256, 256>>>(feature);

    main_kernel<<<NPTS/8, 256>>>(feature, raw, nbr, (float*)d_out);
}

// round 11
// speedup vs baseline: 2.8766x; 1.1145x over previous
#include <cuda_runtime.h>
#include <cstdint>

#define NPTS   131072          // B*N = 2*65536
#define EPSBN  1e-5f

// ---- fragment-ordered bf16 weight tables + folded params (device globals) ----
__device__ __align__(16) uint4  d_fragRaw[4*32];     // raw mlp: K=16(pad of 10), N=32 (4 nt)
__device__ __align__(16) uint4  d_fragR[16*32];      // W_nb bottom: K=32 (2 kc), N=64 (8 nt)
__device__ __align__(16) uint4  d_fragS[32*32];      // w_attn: K=64 (4 kc), N=64 (8 nt)
__device__ __align__(16) float  d_braw[32];
__device__ __align__(16) float  d_bnb[64];
__device__ __align__(16) float2 d_wnbt2[32*32];      // W_nb top (for G), pair (c, c+32)
__device__ __align__(16) float2 d_wout2[64*32];
__device__ __align__(16) float2 d_bout2[32];
__device__ __align__(16) float2 d_wsc2[32*32];
__device__ __align__(16) float2 d_bsc2[32];
__device__ __align__(16) float  d_G[(size_t)NPTS*64]; // G = feature @ W_nb_top' (~33.5MB, L2)

union F2U { float2 f; unsigned long long u; };
__device__ __forceinline__ unsigned long long packdup(float a){
    unsigned long long r; asm("mov.b64 %0, {%1, %1};" : "=l"(r) : "f"(a)); return r;
}
__device__ __forceinline__ void ffma2(unsigned long long& d, unsigned long long a, unsigned long long b){
    asm("fma.rn.f32x2 %0, %1, %2, %0;" : "+l"(d) : "l"(a), "l"(b));
}
__device__ __forceinline__ float lrelu(float x){ return fmaxf(x, 0.2f*x); }

// pack two fp32 into bf16x2: low half = lo, high half = hi
__device__ __forceinline__ uint32_t pack_bf16x2(float lo, float hi){
    uint32_t r; asm("cvt.rn.bf16x2.f32 %0, %1, %2;" : "=r"(r) : "f"(hi), "f"(lo)); return r;
}
// split fp32 pair into bf16 hi + bf16 residual (3-split precision: ~2^-17)
__device__ __forceinline__ void split_pair(float x0, float x1, uint32_t& ah, uint32_t& al){
    ah = pack_bf16x2(x0, x1);
    float h0 = __uint_as_float(ah << 16);
    float h1 = __uint_as_float(ah & 0xFFFF0000u);
    al = pack_bf16x2(x0 - h0, x1 - h1);
}
__device__ __forceinline__ void mma_bf16(float* d, const uint32_t* a, uint32_t b0, uint32_t b1){
    asm volatile("mma.sync.aligned.m16n8k16.row.col.f32.bf16.bf16.f32 "
        "{%0,%1,%2,%3},{%4,%5,%6,%7},{%8,%9},{%0,%1,%2,%3};"
        : "+f"(d[0]),"+f"(d[1]),"+f"(d[2]),"+f"(d[3])
        : "r"(a[0]),"r"(a[1]),"r"(a[2]),"r"(a[3]),"r"(b0),"r"(b1));
}
__device__ __forceinline__ void mma3(float* d, const uint32_t* ah, const uint32_t* al, uint4 b){
    mma_bf16(d, ah, b.x, b.y);   // Ah*Bh
    mma_bf16(d, al, b.x, b.y);   // Al*Bh
    mma_bf16(d, ah, b.z, b.w);   // Ah*Bl
}
// build A-frags (ah/al) from two adjacent fp32 D-tiles (register chaining)
__device__ __forceinline__ void dfrags_to_afrags(const float* dA, const float* dB,
                                                 uint32_t* ah, uint32_t* al){
    split_pair(dA[0], dA[1], ah[0], al[0]);   // row g,   k 2t,2t+1
    split_pair(dA[2], dA[3], ah[1], al[1]);   // row g+8, k 2t,2t+1
    split_pair(dB[0], dB[1], ah[2], al[2]);   // row g,   k 2t+8,2t+9
    split_pair(dB[2], dB[3], ah[3], al[3]);   // row g+8, k 2t+8,2t+9
}

// ---- Kernel 0: fold BN into weights; build bf16 fragment tables. ----
__global__ void __launch_bounds__(1024) fold_kernel(
    const float* w_raw, const float* b_raw, const float* g_raw, const float* be_raw,
    const float* m_raw, const float* v_raw,
    const float* w_nb,  const float* b_nb,  const float* g_nb,  const float* be_nb,
    const float* m_nb,  const float* v_nb,  const float* w_attn,
    const float* w_out, const float* b_out, const float* g_out, const float* be_out,
    const float* m_out, const float* v_out,
    const float* w_sc,  const float* b_sc,  const float* g_sc,  const float* be_sc,
    const float* m_sc,  const float* v_sc)
{
    const int t0 = threadIdx.x;
    const int lane = t0 & 31, gg = lane >> 2, tt = lane & 3;

    // fragRaw: 128 entries (nt 0..3). K rows 2t,2t+1 (b0) and 2t+8,2t+9 (b1); k>=10 -> 0
    if (t0 < 128){
        int nt = t0 >> 5, n = nt*8 + gg;
        float sn = g_raw[n]*rsqrtf(v_raw[n]+EPSBN);
        int k0 = 2*tt, k2 = 2*tt + 8;
        float w0 = w_raw[k0*32+n]*sn;
        float w1 = w_raw[(k0+1)*32+n]*sn;
        float w2 = (k2   < 10) ? w_raw[k2*32+n]*sn     : 0.f;
        float w3 = (k2+1 < 10) ? w_raw[(k2+1)*32+n]*sn : 0.f;
        uint32_t h0,l0,h1,l1; split_pair(w0,w1,h0,l0); split_pair(w2,w3,h1,l1);
        d_fragRaw[t0] = make_uint4(h0,h1,l0,l1);
    }
    // fragR: 512 entries (entry = kc*8+nt)
    if (t0 < 512){
        int entry = t0 >> 5, nt = entry & 7, kc = entry >> 3, n = nt*8 + gg;
        float sn = g_nb[n]*rsqrtf(v_nb[n]+EPSBN);
        int k0 = kc*16 + 2*tt;
        float w0 = w_nb[(32+k0)*64+n]*sn,   w1 = w_nb[(32+k0+1)*64+n]*sn;
        float w2 = w_nb[(32+k0+8)*64+n]*sn, w3 = w_nb[(32+k0+9)*64+n]*sn;
        uint32_t h0,l0,h1,l1; split_pair(w0,w1,h0,l0); split_pair(w2,w3,h1,l1);
        d_fragR[t0] = make_uint4(h0,h1,l0,l1);
    }
    // fragS: 1024 entries (entry = kc*8+nt, kc 0..3)
    {
        int entry = t0 >> 5, nt = entry & 7, kc = entry >> 3, n = nt*8 + gg;
        int k0 = kc*16 + 2*tt;
        float w0 = w_attn[k0*64+n],     w1 = w_attn[(k0+1)*64+n];
        float w2 = w_attn[(k0+8)*64+n], w3 = w_attn[(k0+9)*64+n];
        uint32_t h0,l0,h1,l1; split_pair(w0,w1,h0,l0); split_pair(w2,w3,h1,l1);
        d_fragS[t0] = make_uint4(h0,h1,l0,l1);
    }
    // W_nb top (paired) for g_kernel: 1024 entries
    {
        int k = t0/32, p = t0%32;
        float s0 = g_nb[p]*rsqrtf(v_nb[p]+EPSBN);
        float s1 = g_nb[p+32]*rsqrtf(v_nb[p+32]+EPSBN);
        d_wnbt2[k*32+p] = make_float2(w_nb[k*64+p]*s0, w_nb[k*64+p+32]*s1);
    }
    // w_out (2048: 2/thread), w_sc (1024)
    {
        int p = t0 % 32;
        float so0 = g_out[p]*rsqrtf(v_out[p]+EPSBN);
        float so1 = g_out[p+32]*rsqrtf(v_out[p+32]+EPSBN);
        #pragma unroll
        for (int half = 0; half < 2; half++){
            int e = t0 + half*1024;
            int k = e / 32;
            d_wout2[k*32+p] = make_float2(w_out[k*64+p]*so0, w_out[k*64+p+32]*so1);
        }
        int k = t0 / 32;
        float ss0 = g_sc[p]*rsqrtf(v_sc[p]+EPSBN);
        float ss1 = g_sc[p+32]*rsqrtf(v_sc[p+32]+EPSBN);
        d_wsc2[k*32+p] = make_float2(w_sc[k*64+p]*ss0, w_sc[k*64+p+32]*ss1);
    }
    // biases
    if (t0 < 64){
        int p = t0;
        float s = g_nb[p]*rsqrtf(v_nb[p]+EPSBN);
        d_bnb[p] = (b_nb[p]-m_nb[p])*s + be_nb[p];
    }
    if (t0 < 32){
        int p = t0;
        float sr = g_raw[p]*rsqrtf(v_raw[p]+EPSBN);
        d_braw[p] = (b_raw[p]-m_raw[p])*sr + be_raw[p];
        float so0 = g_out[p]*rsqrtf(v_out[p]+EPSBN);
        float so1 = g_out[p+32]*rsqrtf(v_out[p+32]+EPSBN);
        d_bout2[p] = make_float2((b_out[p]-m_out[p])*so0+be_out[p],
                                 (b_out[p+32]-m_out[p+32])*so1+be_out[p+32]);
        float ss0 = g_sc[p]*rsqrtf(v_sc[p]+EPSBN);
        float ss1 = g_sc[p+32]*rsqrtf(v_sc[p+32]+EPSBN);
        d_bsc2[p] = make_float2((b_sc[p]-m_sc[p])*ss0+be_sc[p],
                                (b_sc[p+32]-m_sc[p+32])*ss1+be_sc[p+32]);
    }
}

// ---- Kernel 1: G = feature @ W_nb_top' (natural [pt][64] layout). ----
__global__ void __launch_bounds__(256) g_kernel(const float* __restrict__ feature)
{
    __shared__ float2 sw[32*32];
    for (int i = threadIdx.x; i < 1024; i += 256) sw[i] = d_wnbt2[i];
    __syncthreads();
    const int gidx = blockIdx.x*256 + threadIdx.x;
    const int pt = gidx >> 5, lane = gidx & 31;
    const float f = feature[pt*32 + lane];
    F2U acc; acc.f = make_float2(0.f, 0.f);
    #pragma unroll
    for (int k=0;k<32;k++){
        F2U wv; wv.f = sw[k*32+lane];
        ffma2(acc.u, packdup(__shfl_sync(0xffffffffu, f, k)), wv.u);
    }
    d_G[(size_t)pt*64 + lane]      = acc.f.x;
    d_G[(size_t)pt*64 + lane + 32] = acc.f.y;
}

// ---- Kernel 2: fused main. One warp/point; bf16 3-split m16n8k16 GEMM chain. ----
// mma lane roles: g = lane>>2 (0..7), t = lane&3 (0..3).
// D frag: c0=(g,2t) c1=(g,2t+1) c2=(g+8,2t) c3=(g+8,2t+1)
// A frag (k16): a0=(g,2t..2t+1) a1=(g+8,2t..) a2=(g,2t+8..) a3=(g+8,2t+8..)
__global__ void __launch_bounds__(128, 3) main_kernel(
    const float* __restrict__ feature,
    const float* __restrict__ raw,
    const int*   __restrict__ nbr,
    float*       __restrict__ outp)
{
    __shared__ __align__(16) float poolS[4][64];

    const int tid = threadIdx.x, lane = tid & 31, w = tid >> 5;
    const int g = lane >> 2, t = lane & 3;
    float* const pool = poolS[w];

    const int pt = blockIdx.x*4 + w;
    const int bbase = (pt >> 16) << 16;     // batch offset (N=65536)

    int idxv = 0;
    if (lane < 16) idxv = nbr[pt*16 + lane];
    const int jr0 = __shfl_sync(0xffffffffu, idxv, g);
    const int jr1 = __shfl_sync(0xffffffffu, idxv, g+8);

    // ---- raw A-frags straight from gmem (row m = 5 float2 of k-pairs) ----
    const float2* raw2 = (const float2*)raw + (size_t)pt*80;
    uint32_t ah[4], al[4];
    {
        float2 p0 = raw2[g*5 + t];
        float2 p1 = raw2[(g+8)*5 + t];
        float2 p2 = (t==0) ? raw2[g*5 + 4]     : make_float2(0.f,0.f);
        float2 p3 = (t==0) ? raw2[(g+8)*5 + 4] : make_float2(0.f,0.f);
        split_pair(p0.x, p0.y, ah[0], al[0]);
        split_pair(p1.x, p1.y, ah[1], al[1]);
        split_pair(p2.x, p2.y, ah[2], al[2]);
        split_pair(p3.x, p3.y, ah[3], al[3]);
    }

    // ---- raw mlp: rmD(16x32) = raw(16x16) @ Wraw + braw; lrelu in place ----
    float rmD[4][4];
    #pragma unroll
    for (int nt=0;nt<4;nt++){
        float2 b = *(const float2*)&d_braw[nt*8 + 2*t];
        rmD[nt][0]=b.x; rmD[nt][1]=b.y; rmD[nt][2]=b.x; rmD[nt][3]=b.y;
    }
    #pragma unroll
    for (int nt=0;nt<4;nt++)
        mma3(rmD[nt], ah, al, d_fragRaw[nt*32 + lane]);
    #pragma unroll
    for (int nt=0;nt<4;nt++)
        #pragma unroll
        for (int i=0;i<4;i++) rmD[nt][i] = lrelu(rmD[nt][i]);

    // ---- prefetch G rows (L2 latency overlaps the R-GEMM mma block below) ----
    float2 ga[8], gb[8];
    {
        const float* G0 = d_G + (size_t)(bbase + jr0)*64;
        const float* G1 = d_G + (size_t)(bbase + jr1)*64;
        #pragma unroll
        for (int nt=0;nt<8;nt++){
            ga[nt] = *(const float2*)&G0[nt*8 + 2*t];
            gb[nt] = *(const float2*)&G1[nt*8 + 2*t];
        }
    }

    // ---- R-GEMM: hv(16x64) = rm(16x32) @ W_nbb + bnb  (A from rmD tiles) ----
    float hv[8][4];
    #pragma unroll
    for (int nt=0;nt<8;nt++){
        float2 b = *(const float2*)&d_bnb[nt*8 + 2*t];
        hv[nt][0]=b.x; hv[nt][1]=b.y; hv[nt][2]=b.x; hv[nt][3]=b.y;
    }
    #pragma unroll
    for (int kc=0;kc<2;kc++){
        dfrags_to_afrags(rmD[2*kc], rmD[2*kc+1], ah, al);
        #pragma unroll
        for (int nt=0;nt<8;nt++)
            mma3(hv[nt], ah, al, d_fragR[(kc*8+nt)*32 + lane]);
    }

    // ---- h = lrelu(G + hv), in place ----
    #pragma unroll
    for (int nt=0;nt<8;nt++){
        hv[nt][0] = lrelu(hv[nt][0] + ga[nt].x);
        hv[nt][1] = lrelu(hv[nt][1] + ga[nt].y);
        hv[nt][2] = lrelu(hv[nt][2] + gb[nt].x);
        hv[nt][3] = lrelu(hv[nt][3] + gb[nt].y);
    }

    // ---- s-GEMM: sD(16x64) = h(16x64) @ w_attn  (A from hv tiles) ----
    float sD[8][4];
    #pragma unroll
    for (int nt=0;nt<8;nt++){ sD[nt][0]=0.f; sD[nt][1]=0.f; sD[nt][2]=0.f; sD[nt][3]=0.f; }
    #pragma unroll 1
    for (int kc=0;kc<4;kc++){
        dfrags_to_afrags(hv[2*kc], hv[2*kc+1], ah, al);
        #pragma unroll
        for (int nt=0;nt<8;nt++)
            mma3(sD[nt], ah, al, d_fragS[(kc*8+nt)*32 + lane]);
    }

    // ---- softmax over 16 neighbors (no max shift) + pooling, split-ownership reduce ----
    // Per nt this lane holds rows g,g+8 of channels c0=nt*8+2t and c1=c0+1.
    float Kd[8], Kn[8];
    const bool gb0 = (lane & 4) != 0;
    #pragma unroll
    for (int nt=0;nt<8;nt++){
        float e0=__expf(sD[nt][0]), e1=__expf(sD[nt][1]);
        float e2=__expf(sD[nt][2]), e3=__expf(sD[nt][3]);
        float den0 = e0+e2, num0 = fmaf(e0, hv[nt][0], e2*hv[nt][2]);
        float den1 = e1+e3, num1 = fmaf(e1, hv[nt][1], e3*hv[nt][3]);
        // round A (xor 4): low g-bit0 keeps parity 0, high keeps parity 1
        float sd = gb0 ? den0 : den1;
        float sn = gb0 ? num0 : num1;
        float rd = __shfl_xor_sync(0xffffffffu, sd, 4);
        float rn = __shfl_xor_sync(0xffffffffu, sn, 4);
        Kd[nt] = (gb0 ? den1 : den0) + rd;
        Kn[nt] = (gb0 ? num1 : num0) + rn;
    }
    const bool gb1 = (lane & 8) != 0;
    float Ld[4], Ln[4];
    #pragma unroll
    for (int j=0;j<4;j++){
        float sd = gb1 ? Kd[j] : Kd[j+4];
        float sn = gb1 ? Kn[j] : Kn[j+4];
        float rd = __shfl_xor_sync(0xffffffffu, sd, 8);
        float rn = __shfl_xor_sync(0xffffffffu, sn, 8);
        Ld[j] = (gb1 ? Kd[j+4] : Kd[j]) + rd;
        Ln[j] = (gb1 ? Kn[j+4] : Kn[j]) + rn;
    }
    const bool gb2 = (lane & 16) != 0;
    #pragma unroll
    for (int j=0;j<2;j++){
        float sd = gb2 ? Ld[j] : Ld[j+2];
        float sn = gb2 ? Ln[j] : Ln[j+2];
        float rd = __shfl_xor_sync(0xffffffffu, sd, 16);
        float rn = __shfl_xor_sync(0xffffffffu, sn, 16);
        float md = (gb2 ? Ld[j+2] : Ld[j]) + rd;
        float mn = (gb2 ? Ln[j+2] : Ln[j]) + rn;
        int nt = j + (gb2 ? 2 : 0) + (gb1 ? 4 : 0);
        int c  = nt*8 + 2*t + (gb0 ? 1 : 0);
        pool[c] = __fdividef(mn, md);
    }
    __syncwarp();

    // ---- out = pooled @ w_out' + b_out'; sc = feature @ w_sc' + b_sc' ----
    F2U oacc; oacc.f = d_bout2[lane];
    #pragma unroll 8
    for (int p=0;p<64;p++){
        F2U wv; wv.f = d_wout2[p*32 + lane];
        ffma2(oacc.u, packdup(pool[p]), wv.u);
    }
    F2U sacc; sacc.f = d_bsc2[lane];
    const float fv = feature[pt*32 + lane];
    #pragma unroll 8
    for (int k=0;k<32;k++){
        F2U wv; wv.f = d_wsc2[k*32 + lane];
        ffma2(sacc.u, packdup(__shfl_sync(0xffffffffu, fv, k)), wv.u);
    }

    outp[pt*64 + lane]      = lrelu(sacc.f.x + oacc.f.x);
    outp[pt*64 + lane + 32] = lrelu(sacc.f.y + oacc.f.y);
}

extern "C" void kernel_launch(void* const* d_in, const int* in_sizes, int n_in,
                              void* d_out, int out_size)
{
    const float* feature = (const float*)d_in[0];
    const float* raw     = (const float*)d_in[1];
    const int*   nbr     = (const int*)  d_in[2];

    fold_kernel<<<1, 1024>>>(
        (const float*)d_in[3],  (const float*)d_in[4],  (const float*)d_in[5],
        (const float*)d_in[6],  (const float*)d_in[7],  (const float*)d_in[8],
        (const float*)d_in[9],  (const float*)d_in[10], (const float*)d_in[11],
        (const float*)d_in[12], (const float*)d_in[13], (const float*)d_in[14],
        (const float*)d_in[15],
        (const float*)d_in[16], (const float*)d_in[17], (const float*)d_in[18],
        (const float*)d_in[19], (const float*)d_in[20], (const float*)d_in[21],
        (const float*)d_in[22], (const float*)d_in[23], (const float*)d_in[24],
        (const float*)d_in[25], (const float*)d_in[26], (const float*)d_in[27]);

    g_kernel<<<(NPTS*32)/256, 256>>>(feature);

    main_kernel<<<NPTS/4, 128>>>(feature, raw, nbr, (float*)d_out);
}

// round 12
// speedup vs baseline: 3.3137x; 1.1520x over previous
#include <cuda_runtime.h>
#include <cstdint>

#define NPTS   131072          // B*N = 2*65536
#define EPSBN  1e-5f

// ---- fragment-ordered bf16 weight tables + folded params (device globals) ----
__device__ __align__(16) uint4  d_fragRaw[4*32];     // raw mlp: K=16(pad of 10), N=32 (4 nt)
__device__ __align__(16) uint4  d_fragR[16*32];      // W_nb bottom: K=32 (2 kc), N=64 (8 nt)
__device__ __align__(16) uint4  d_fragS[32*32];      // w_attn: K=64 (4 kc), N=64 (8 nt)
__device__ __align__(16) uint4  d_fragOut[32*32];    // w_out folded: K=64 (4 kc), N=64 (8 nt)
__device__ __align__(16) float  d_braw[32];
__device__ __align__(16) float  d_bnb[64];
__device__ __align__(16) float  d_boutN[64];
__device__ __align__(16) float2 d_wnbt2[32*32];      // W_nb top (for G), pair (c, c+32)
__device__ __align__(16) float2 d_wsc2[32*32];
__device__ __align__(16) float2 d_bsc2[32];
__device__ __align__(16) float  d_G[(size_t)NPTS*64];  // feature @ W_nb_top'   (~33.5MB)
__device__ __align__(16) float  d_SC[(size_t)NPTS*64]; // feature @ w_sc' + b   (~33.5MB)
__device__ __align__(16) float  d_P[(size_t)NPTS*64];  // pooled                (~33.5MB)

union F2U { float2 f; unsigned long long u; };
__device__ __forceinline__ unsigned long long packdup(float a){
    unsigned long long r; asm("mov.b64 %0, {%1, %1};" : "=l"(r) : "f"(a)); return r;
}
__device__ __forceinline__ void ffma2(unsigned long long& d, unsigned long long a, unsigned long long b){
    asm("fma.rn.f32x2 %0, %1, %2, %0;" : "+l"(d) : "l"(a), "l"(b));
}
__device__ __forceinline__ float lrelu(float x){ return fmaxf(x, 0.2f*x); }

__device__ __forceinline__ uint32_t pack_bf16x2(float lo, float hi){
    uint32_t r; asm("cvt.rn.bf16x2.f32 %0, %1, %2;" : "=r"(r) : "f"(hi), "f"(lo)); return r;
}
// split fp32 pair into bf16 hi + bf16 residual (3-split precision: ~2^-17)
__device__ __forceinline__ void split_pair(float x0, float x1, uint32_t& ah, uint32_t& al){
    ah = pack_bf16x2(x0, x1);
    float h0 = __uint_as_float(ah << 16);
    float h1 = __uint_as_float(ah & 0xFFFF0000u);
    al = pack_bf16x2(x0 - h0, x1 - h1);
}
__device__ __forceinline__ void mma_bf16(float* d, const uint32_t* a, uint32_t b0, uint32_t b1){
    asm volatile("mma.sync.aligned.m16n8k16.row.col.f32.bf16.bf16.f32 "
        "{%0,%1,%2,%3},{%4,%5,%6,%7},{%8,%9},{%0,%1,%2,%3};"
        : "+f"(d[0]),"+f"(d[1]),"+f"(d[2]),"+f"(d[3])
        : "r"(a[0]),"r"(a[1]),"r"(a[2]),"r"(a[3]),"r"(b0),"r"(b1));
}
__device__ __forceinline__ void mma3(float* d, const uint32_t* ah, const uint32_t* al, uint4 b){
    mma_bf16(d, ah, b.x, b.y);
    mma_bf16(d, al, b.x, b.y);
    mma_bf16(d, ah, b.z, b.w);
}
__device__ __forceinline__ void dfrags_to_afrags(const float* dA, const float* dB,
                                                 uint32_t* ah, uint32_t* al){
    split_pair(dA[0], dA[1], ah[0], al[0]);
    split_pair(dA[2], dA[3], ah[1], al[1]);
    split_pair(dB[0], dB[1], ah[2], al[2]);
    split_pair(dB[2], dB[3], ah[3], al[3]);
}

// ---- Kernel 0: fold BN into weights; build bf16 fragment tables. ----
__global__ void __launch_bounds__(1024) fold_kernel(
    const float* w_raw, const float* b_raw, const float* g_raw, const float* be_raw,
    const float* m_raw, const float* v_raw,
    const float* w_nb,  const float* b_nb,  const float* g_nb,  const float* be_nb,
    const float* m_nb,  const float* v_nb,  const float* w_attn,
    const float* w_out, const float* b_out, const float* g_out, const float* be_out,
    const float* m_out, const float* v_out,
    const float* w_sc,  const float* b_sc,  const float* g_sc,  const float* be_sc,
    const float* m_sc,  const float* v_sc)
{
    const int t0 = threadIdx.x;
    const int lane = t0 & 31, gg = lane >> 2, tt = lane & 3;

    // fragRaw: 128 entries (nt 0..3); k>=10 -> 0
    if (t0 < 128){
        int nt = t0 >> 5, n = nt*8 + gg;
        float sn = g_raw[n]*rsqrtf(v_raw[n]+EPSBN);
        int k0 = 2*tt, k2 = 2*tt + 8;
        float w0 = w_raw[k0*32+n]*sn;
        float w1 = w_raw[(k0+1)*32+n]*sn;
        float w2 = (k2   < 10) ? w_raw[k2*32+n]*sn     : 0.f;
        float w3 = (k2+1 < 10) ? w_raw[(k2+1)*32+n]*sn : 0.f;
        uint32_t h0,l0,h1,l1; split_pair(w0,w1,h0,l0); split_pair(w2,w3,h1,l1);
        d_fragRaw[t0] = make_uint4(h0,h1,l0,l1);
    }
    // fragR: 512 entries (entry = kc*8+nt)
    if (t0 < 512){
        int entry = t0 >> 5, nt = entry & 7, kc = entry >> 3, n = nt*8 + gg;
        float sn = g_nb[n]*rsqrtf(v_nb[n]+EPSBN);
        int k0 = kc*16 + 2*tt;
        float w0 = w_nb[(32+k0)*64+n]*sn,   w1 = w_nb[(32+k0+1)*64+n]*sn;
        float w2 = w_nb[(32+k0+8)*64+n]*sn, w3 = w_nb[(32+k0+9)*64+n]*sn;
        uint32_t h0,l0,h1,l1; split_pair(w0,w1,h0,l0); split_pair(w2,w3,h1,l1);
        d_fragR[t0] = make_uint4(h0,h1,l0,l1);
    }
    // fragS: 1024 entries (entry = kc*8+nt, kc 0..3)
    {
        int entry = t0 >> 5, nt = entry & 7, kc = entry >> 3, n = nt*8 + gg;
        int k0 = kc*16 + 2*tt;
        float w0 = w_attn[k0*64+n],     w1 = w_attn[(k0+1)*64+n];
        float w2 = w_attn[(k0+8)*64+n], w3 = w_attn[(k0+9)*64+n];
        uint32_t h0,l0,h1,l1; split_pair(w0,w1,h0,l0); split_pair(w2,w3,h1,l1);
        d_fragS[t0] = make_uint4(h0,h1,l0,l1);
    }
    // fragOut: 1024 entries, folded w_out
    {
        int entry = t0 >> 5, nt = entry & 7, kc = entry >> 3, n = nt*8 + gg;
        float sn = g_out[n]*rsqrtf(v_out[n]+EPSBN);
        int k0 = kc*16 + 2*tt;
        float w0 = w_out[k0*64+n]*sn,     w1 = w_out[(k0+1)*64+n]*sn;
        float w2 = w_out[(k0+8)*64+n]*sn, w3 = w_out[(k0+9)*64+n]*sn;
        uint32_t h0,l0,h1,l1; split_pair(w0,w1,h0,l0); split_pair(w2,w3,h1,l1);
        d_fragOut[t0] = make_uint4(h0,h1,l0,l1);
    }
    // W_nb top (paired) + w_sc (paired)
    {
        int k = t0/32, p = t0%32;
        float s0 = g_nb[p]*rsqrtf(v_nb[p]+EPSBN);
        float s1 = g_nb[p+32]*rsqrtf(v_nb[p+32]+EPSBN);
        d_wnbt2[k*32+p] = make_float2(w_nb[k*64+p]*s0, w_nb[k*64+p+32]*s1);
        float ss0 = g_sc[p]*rsqrtf(v_sc[p]+EPSBN);
        float ss1 = g_sc[p+32]*rsqrtf(v_sc[p+32]+EPSBN);
        d_wsc2[k*32+p] = make_float2(w_sc[k*64+p]*ss0, w_sc[k*64+p+32]*ss1);
    }
    // biases
    if (t0 < 64){
        int p = t0;
        float s = g_nb[p]*rsqrtf(v_nb[p]+EPSBN);
        d_bnb[p] = (b_nb[p]-m_nb[p])*s + be_nb[p];
        float so = g_out[p]*rsqrtf(v_out[p]+EPSBN);
        d_boutN[p] = (b_out[p]-m_out[p])*so + be_out[p];
    }
    if (t0 < 32){
        int p = t0;
        float sr = g_raw[p]*rsqrtf(v_raw[p]+EPSBN);
        d_braw[p] = (b_raw[p]-m_raw[p])*sr + be_raw[p];
        float ss0 = g_sc[p]*rsqrtf(v_sc[p]+EPSBN);
        float ss1 = g_sc[p+32]*rsqrtf(v_sc[p+32]+EPSBN);
        d_bsc2[p] = make_float2((b_sc[p]-m_sc[p])*ss0+be_sc[p],
                                (b_sc[p+32]-m_sc[p+32])*ss1+be_sc[p+32]);
    }
}

// ---- Kernel 1: G = feature @ W_nb_top', SC = feature @ w_sc' + b_sc'. ----
__global__ void __launch_bounds__(256) g_kernel(const float* __restrict__ feature)
{
    __shared__ float2 swG[32*32];
    __shared__ float2 swS[32*32];
    for (int i = threadIdx.x; i < 1024; i += 256){ swG[i] = d_wnbt2[i]; swS[i] = d_wsc2[i]; }
    __syncthreads();
    const int gidx = blockIdx.x*256 + threadIdx.x;
    const int pt = gidx >> 5, lane = gidx & 31;
    const float f = feature[pt*32 + lane];
    F2U accg; accg.f = make_float2(0.f, 0.f);
    F2U accs; accs.f = d_bsc2[lane];
    #pragma unroll
    for (int k=0;k<32;k++){
        unsigned long long ad = packdup(__shfl_sync(0xffffffffu, f, k));
        F2U wg; wg.f = swG[k*32+lane];
        F2U ws; ws.f = swS[k*32+lane];
        ffma2(accg.u, ad, wg.u);
        ffma2(accs.u, ad, ws.u);
    }
    d_G[(size_t)pt*64 + lane]       = accg.f.x;
    d_G[(size_t)pt*64 + lane + 32]  = accg.f.y;
    d_SC[(size_t)pt*64 + lane]      = accs.f.x;
    d_SC[(size_t)pt*64 + lane + 32] = accs.f.y;
}

// ---- Kernel 2: fused main. One warp/point; bf16 3-split m16n8k16 GEMM chain. ----
// mma lane roles: g = lane>>2 (0..7), t = lane&3 (0..3).
__global__ void __launch_bounds__(128, 3) main_kernel(
    const float* __restrict__ raw,
    const int*   __restrict__ nbr)
{
    const int tid = threadIdx.x, lane = tid & 31, w = tid >> 5;
    const int g = lane >> 2, t = lane & 3;

    const int pt = blockIdx.x*4 + w;
    const int bbase = (pt >> 16) << 16;     // batch offset (N=65536)

    int idxv = 0;
    if (lane < 16) idxv = nbr[pt*16 + lane];
    const int jr0 = __shfl_sync(0xffffffffu, idxv, g);
    const int jr1 = __shfl_sync(0xffffffffu, idxv, g+8);

    // ---- raw A-frags straight from gmem ----
    const float2* raw2 = (const float2*)raw + (size_t)pt*80;
    uint32_t ah[4], al[4];
    {
        float2 p0 = raw2[g*5 + t];
        float2 p1 = raw2[(g+8)*5 + t];
        float2 p2 = (t==0) ? raw2[g*5 + 4]     : make_float2(0.f,0.f);
        float2 p3 = (t==0) ? raw2[(g+8)*5 + 4] : make_float2(0.f,0.f);
        split_pair(p0.x, p0.y, ah[0], al[0]);
        split_pair(p1.x, p1.y, ah[1], al[1]);
        split_pair(p2.x, p2.y, ah[2], al[2]);
        split_pair(p3.x, p3.y, ah[3], al[3]);
    }

    // ---- raw mlp: rmD(16x32) = raw(16x16) @ Wraw + braw; lrelu in place ----
    float rmD[4][4];
    #pragma unroll
    for (int nt=0;nt<4;nt++){
        float2 b = *(const float2*)&d_braw[nt*8 + 2*t];
        rmD[nt][0]=b.x; rmD[nt][1]=b.y; rmD[nt][2]=b.x; rmD[nt][3]=b.y;
    }
    #pragma unroll
    for (int nt=0;nt<4;nt++)
        mma3(rmD[nt], ah, al, d_fragRaw[nt*32 + lane]);
    #pragma unroll
    for (int nt=0;nt<4;nt++)
        #pragma unroll
        for (int i=0;i<4;i++) rmD[nt][i] = lrelu(rmD[nt][i]);

    // ---- prefetch G rows (L2 latency overlaps the R-GEMM mma block below) ----
    float2 ga[8], gb[8];
    {
        const float* G0 = d_G + (size_t)(bbase + jr0)*64;
        const float* G1 = d_G + (size_t)(bbase + jr1)*64;
        #pragma unroll
        for (int nt=0;nt<8;nt++){
            ga[nt] = *(const float2*)&G0[nt*8 + 2*t];
            gb[nt] = *(const float2*)&G1[nt*8 + 2*t];
        }
    }

    // ---- R-GEMM: hv(16x64) = rm(16x32) @ W_nbb + bnb ----
    float hv[8][4];
    #pragma unroll
    for (int nt=0;nt<8;nt++){
        float2 b = *(const float2*)&d_bnb[nt*8 + 2*t];
        hv[nt][0]=b.x; hv[nt][1]=b.y; hv[nt][2]=b.x; hv[nt][3]=b.y;
    }
    #pragma unroll
    for (int kc=0;kc<2;kc++){
        dfrags_to_afrags(rmD[2*kc], rmD[2*kc+1], ah, al);
        #pragma unroll
        for (int nt=0;nt<8;nt++)
            mma3(hv[nt], ah, al, d_fragR[(kc*8+nt)*32 + lane]);
    }

    // ---- h = lrelu(G + hv), in place ----
    #pragma unroll
    for (int nt=0;nt<8;nt++){
        hv[nt][0] = lrelu(hv[nt][0] + ga[nt].x);
        hv[nt][1] = lrelu(hv[nt][1] + ga[nt].y);
        hv[nt][2] = lrelu(hv[nt][2] + gb[nt].x);
        hv[nt][3] = lrelu(hv[nt][3] + gb[nt].y);
    }

    // ---- s-GEMM: sD(16x64) = h(16x64) @ w_attn ----
    float sD[8][4];
    #pragma unroll
    for (int nt=0;nt<8;nt++){ sD[nt][0]=0.f; sD[nt][1]=0.f; sD[nt][2]=0.f; sD[nt][3]=0.f; }
    #pragma unroll 1
    for (int kc=0;kc<4;kc++){
        dfrags_to_afrags(hv[2*kc], hv[2*kc+1], ah, al);
        #pragma unroll
        for (int nt=0;nt<8;nt++)
            mma3(sD[nt], ah, al, d_fragS[(kc*8+nt)*32 + lane]);
    }

    // ---- softmax over 16 neighbors + pooling, split-ownership reduce; write d_P ----
    float Kd[8], Kn[8];
    const bool gb0 = (lane & 4) != 0;
    #pragma unroll
    for (int nt=0;nt<8;nt++){
        float e0=__expf(sD[nt][0]), e1=__expf(sD[nt][1]);
        float e2=__expf(sD[nt][2]), e3=__expf(sD[nt][3]);
        float den0 = e0+e2, num0 = fmaf(e0, hv[nt][0], e2*hv[nt][2]);
        float den1 = e1+e3, num1 = fmaf(e1, hv[nt][1], e3*hv[nt][3]);
        float sd = gb0 ? den0 : den1;
        float sn = gb0 ? num0 : num1;
        float rd = __shfl_xor_sync(0xffffffffu, sd, 4);
        float rn = __shfl_xor_sync(0xffffffffu, sn, 4);
        Kd[nt] = (gb0 ? den1 : den0) + rd;
        Kn[nt] = (gb0 ? num1 : num0) + rn;
    }
    const bool gb1 = (lane & 8) != 0;
    float Ld[4], Ln[4];
    #pragma unroll
    for (int j=0;j<4;j++){
        float sd = gb1 ? Kd[j] : Kd[j+4];
        float sn = gb1 ? Kn[j] : Kn[j+4];
        float rd = __shfl_xor_sync(0xffffffffu, sd, 8);
        float rn = __shfl_xor_sync(0xffffffffu, sn, 8);
        Ld[j] = (gb1 ? Kd[j+4] : Kd[j]) + rd;
        Ln[j] = (gb1 ? Kn[j+4] : Kn[j]) + rn;
    }
    const bool gb2 = (lane & 16) != 0;
    #pragma unroll
    for (int j=0;j<2;j++){
        float sd = gb2 ? Ld[j] : Ld[j+2];
        float sn = gb2 ? Ln[j] : Ln[j+2];
        float rd = __shfl_xor_sync(0xffffffffu, sd, 16);
        float rn = __shfl_xor_sync(0xffffffffu, sn, 16);
        float md = (gb2 ? Ld[j+2] : Ld[j]) + rd;
        float mn = (gb2 ? Ln[j+2] : Ln[j]) + rn;
        int nt = j + (gb2 ? 2 : 0) + (gb1 ? 4 : 0);
        int c  = nt*8 + 2*t + (gb0 ? 1 : 0);
        d_P[(size_t)pt*64 + c] = __fdividef(mn, md);
    }
}

// ---- Kernel 3: out = lrelu(SC + pooled @ w_out' + b_out'). 16 points/warp. ----
__global__ void __launch_bounds__(256) out_kernel(float* __restrict__ outp)
{
    const int tid = threadIdx.x, lane = tid & 31, w = tid >> 5;
    const int g = lane >> 2, t = lane & 3;
    const int ptb = (blockIdx.x*8 + w)*16;

    const float2* P0 = (const float2*)(d_P + (size_t)(ptb+g)*64);
    const float2* P1 = (const float2*)(d_P + (size_t)(ptb+g+8)*64);

    float D[8][4];
    #pragma unroll
    for (int nt=0;nt<8;nt++){
        float2 b = *(const float2*)&d_boutN[nt*8 + 2*t];
        D[nt][0]=b.x; D[nt][1]=b.y; D[nt][2]=b.x; D[nt][3]=b.y;
    }
    uint32_t ah[4], al[4];
    #pragma unroll
    for (int kc=0;kc<4;kc++){
        float2 p0 = P0[kc*8 + t];
        float2 p1 = P1[kc*8 + t];
        float2 p2 = P0[kc*8 + t + 4];
        float2 p3 = P1[kc*8 + t + 4];
        split_pair(p0.x, p0.y, ah[0], al[0]);
        split_pair(p1.x, p1.y, ah[1], al[1]);
        split_pair(p2.x, p2.y, ah[2], al[2]);
        split_pair(p3.x, p3.y, ah[3], al[3]);
        #pragma unroll
        for (int nt=0;nt<8;nt++)
            mma3(D[nt], ah, al, d_fragOut[(kc*8+nt)*32 + lane]);
    }
    const float* S0 = d_SC + (size_t)(ptb+g)*64;
    const float* S1 = d_SC + (size_t)(ptb+g+8)*64;
    #pragma unroll
    for (int nt=0;nt<8;nt++){
        float2 s0 = *(const float2*)&S0[nt*8 + 2*t];
        float2 s1 = *(const float2*)&S1[nt*8 + 2*t];
        *(float2*)&outp[(size_t)(ptb+g)*64   + nt*8 + 2*t] =
            make_float2(lrelu(D[nt][0] + s0.x), lrelu(D[nt][1] + s0.y));
        *(float2*)&outp[(size_t)(ptb+g+8)*64 + nt*8 + 2*t] =
            make_float2(lrelu(D[nt][2] + s1.x), lrelu(D[nt][3] + s1.y));
    }
}

extern "C" void kernel_launch(void* const* d_in, const int* in_sizes, int n_in,
                              void* d_out, int out_size)
{
    const float* feature = (const float*)d_in[0];
    const float* raw     = (const float*)d_in[1];
    const int*   nbr     = (const int*)  d_in[2];

    fold_kernel<<<1, 1024>>>(
        (const float*)d_in[3],  (const float*)d_in[4],  (const float*)d_in[5],
        (const float*)d_in[6],  (const float*)d_in[7],  (const float*)d_in[8],
        (const float*)d_in[9],  (const float*)d_in[10], (const float*)d_in[11],
        (const float*)d_in[12], (const float*)d_in[13], (const float*)d_in[14],
        (const float*)d_in[15],
        (const float*)d_in[16], (const float*)d_in[17], (const float*)d_in[18],
        (const float*)d_in[19], (const float*)d_in[20], (const float*)d_in[21],
        (const float*)d_in[22], (const float*)d_in[23], (const float*)d_in[24],
        (const float*)d_in[25], (const float*)d_in[26], (const float*)d_in[27]);

    g_kernel<<<(NPTS*32)/256, 256>>>(feature);

    main_kernel<<<NPTS/4, 128>>>(raw, nbr);

    out_kernel<<<NPTS/(16*8), 256>>>((float*)d_out);
}

// round 14
// speedup vs baseline: 3.7850x; 1.1422x over previous
#include <cuda_runtime.h>
#include <cstdint>

#define NPTS   131072          // B*N = 2*65536
#define EPSBN  1e-5f

// ---- fragment-ordered bf16 weight tables + folded params (device globals) ----
__device__ __align__(16) uint4  d_fragRaw[4*32];     // raw mlp: K=16(pad of 10), N=32 (4 nt)
__device__ __align__(16) uint4  d_fragR[16*32];      // W_nb bottom: K=32 (2 kc), N=64 (8 nt)
__device__ __align__(16) uint4  d_fragS[32*32];      // w_attn: K=64 (4 kc), N=64 (8 nt)
__device__ __align__(16) uint4  d_fragOut[32*32];    // w_out folded: K=64 (4 kc), N=64 (8 nt)
__device__ __align__(16) float  d_braw[32];
__device__ __align__(16) float  d_bnb[64];
__device__ __align__(16) float  d_boutN[64];
__device__ __align__(16) float2 d_wnbt2[32*32];      // W_nb top (for G), pair (c, c+32)
__device__ __align__(16) float2 d_wsc2[32*32];
__device__ __align__(16) float2 d_bsc2[32];
__device__ __align__(16) float  d_G[(size_t)NPTS*64];  // feature @ W_nb_top'   (~33.5MB)
__device__ __align__(16) float  d_SC[(size_t)NPTS*64]; // feature @ w_sc' + b   (~33.5MB)
__device__ __align__(16) float  d_P[(size_t)NPTS*64];  // pooled                (~33.5MB)

union F2U { float2 f; unsigned long long u; };
__device__ __forceinline__ unsigned long long packdup(float a){
    unsigned long long r; asm("mov.b64 %0, {%1, %1};" : "=l"(r) : "f"(a)); return r;
}
__device__ __forceinline__ void ffma2(unsigned long long& d, unsigned long long a, unsigned long long b){
    asm("fma.rn.f32x2 %0, %1, %2, %0;" : "+l"(d) : "l"(a), "l"(b));
}
__device__ __forceinline__ float lrelu(float x){ return fmaxf(x, 0.2f*x); }

__device__ __forceinline__ uint32_t pack_bf16x2(float lo, float hi){
    uint32_t r; asm("cvt.rn.bf16x2.f32 %0, %1, %2;" : "=r"(r) : "f"(hi), "f"(lo)); return r;
}
// split fp32 pair into bf16 hi + bf16 residual (3-split precision: ~2^-17)
__device__ __forceinline__ void split_pair(float x0, float x1, uint32_t& ah, uint32_t& al){
    ah = pack_bf16x2(x0, x1);
    float h0 = __uint_as_float(ah << 16);
    float h1 = __uint_as_float(ah & 0xFFFF0000u);
    al = pack_bf16x2(x0 - h0, x1 - h1);
}
__device__ __forceinline__ void mma_bf16(float* d, const uint32_t* a, uint32_t b0, uint32_t b1){
    asm volatile("mma.sync.aligned.m16n8k16.row.col.f32.bf16.bf16.f32 "
        "{%0,%1,%2,%3},{%4,%5,%6,%7},{%8,%9},{%0,%1,%2,%3};"
        : "+f"(d[0]),"+f"(d[1]),"+f"(d[2]),"+f"(d[3])
        : "r"(a[0]),"r"(a[1]),"r"(a[2]),"r"(a[3]),"r"(b0),"r"(b1));
}
__device__ __forceinline__ void mma3(float* d, const uint32_t* ah, const uint32_t* al, uint4 b){
    mma_bf16(d, ah, b.x, b.y);
    mma_bf16(d, al, b.x, b.y);
    mma_bf16(d, ah, b.z, b.w);
}
__device__ __forceinline__ void dfrags_to_afrags(const float* dA, const float* dB,
                                                 uint32_t* ah, uint32_t* al){
    split_pair(dA[0], dA[1], ah[0], al[0]);
    split_pair(dA[2], dA[3], ah[1], al[1]);
    split_pair(dB[0], dB[1], ah[2], al[2]);
    split_pair(dB[2], dB[3], ah[3], al[3]);
}

// ---- Kernel 0: fold BN into weights; build bf16 fragment tables. ----
__global__ void __launch_bounds__(1024) fold_kernel(
    const float* w_raw, const float* b_raw, const float* g_raw, const float* be_raw,
    const float* m_raw, const float* v_raw,
    const float* w_nb,  const float* b_nb,  const float* g_nb,  const float* be_nb,
    const float* m_nb,  const float* v_nb,  const float* w_attn,
    const float* w_out, const float* b_out, const float* g_out, const float* be_out,
    const float* m_out, const float* v_out,
    const float* w_sc,  const float* b_sc,  const float* g_sc,  const float* be_sc,
    const float* m_sc,  const float* v_sc)
{
    const int t0 = threadIdx.x;
    const int lane = t0 & 31, gg = lane >> 2, tt = lane & 3;

    // fragRaw: 128 entries (nt 0..3); k>=10 -> 0
    if (t0 < 128){
        int nt = t0 >> 5, n = nt*8 + gg;
        float sn = g_raw[n]*rsqrtf(v_raw[n]+EPSBN);
        int k0 = 2*tt, k2 = 2*tt + 8;
        float w0 = w_raw[k0*32+n]*sn;
        float w1 = w_raw[(k0+1)*32+n]*sn;
        float w2 = (k2   < 10) ? w_raw[k2*32+n]*sn     : 0.f;
        float w3 = (k2+1 < 10) ? w_raw[(k2+1)*32+n]*sn : 0.f;
        uint32_t h0,l0,h1,l1; split_pair(w0,w1,h0,l0); split_pair(w2,w3,h1,l1);
        d_fragRaw[t0] = make_uint4(h0,h1,l0,l1);
    }
    // fragR: 512 entries (entry = kc*8+nt)
    if (t0 < 512){
        int entry = t0 >> 5, nt = entry & 7, kc = entry >> 3, n = nt*8 + gg;
        float sn = g_nb[n]*rsqrtf(v_nb[n]+EPSBN);
        int k0 = kc*16 + 2*tt;
        float w0 = w_nb[(32+k0)*64+n]*sn,   w1 = w_nb[(32+k0+1)*64+n]*sn;
        float w2 = w_nb[(32+k0+8)*64+n]*sn, w3 = w_nb[(32+k0+9)*64+n]*sn;
        uint32_t h0,l0,h1,l1; split_pair(w0,w1,h0,l0); split_pair(w2,w3,h1,l1);
        d_fragR[t0] = make_uint4(h0,h1,l0,l1);
    }
    // fragS: 1024 entries (entry = kc*8+nt, kc 0..3)
    {
        int entry = t0 >> 5, nt = entry & 7, kc = entry >> 3, n = nt*8 + gg;
        int k0 = kc*16 + 2*tt;
        float w0 = w_attn[k0*64+n],     w1 = w_attn[(k0+1)*64+n];
        float w2 = w_attn[(k0+8)*64+n], w3 = w_attn[(k0+9)*64+n];
        uint32_t h0,l0,h1,l1; split_pair(w0,w1,h0,l0); split_pair(w2,w3,h1,l1);
        d_fragS[t0] = make_uint4(h0,h1,l0,l1);
    }
    // fragOut: 1024 entries, folded w_out
    {
        int entry = t0 >> 5, nt = entry & 7, kc = entry >> 3, n = nt*8 + gg;
        float sn = g_out[n]*rsqrtf(v_out[n]+EPSBN);
        int k0 = kc*16 + 2*tt;
        float w0 = w_out[k0*64+n]*sn,     w1 = w_out[(k0+1)*64+n]*sn;
        float w2 = w_out[(k0+8)*64+n]*sn, w3 = w_out[(k0+9)*64+n]*sn;
        uint32_t h0,l0,h1,l1; split_pair(w0,w1,h0,l0); split_pair(w2,w3,h1,l1);
        d_fragOut[t0] = make_uint4(h0,h1,l0,l1);
    }
    // W_nb top (paired) + w_sc (paired)
    {
        int k = t0/32, p = t0%32;
        float s0 = g_nb[p]*rsqrtf(v_nb[p]+EPSBN);
        float s1 = g_nb[p+32]*rsqrtf(v_nb[p+32]+EPSBN);
        d_wnbt2[k*32+p] = make_float2(w_nb[k*64+p]*s0, w_nb[k*64+p+32]*s1);
        float ss0 = g_sc[p]*rsqrtf(v_sc[p]+EPSBN);
        float ss1 = g_sc[p+32]*rsqrtf(v_sc[p+32]+EPSBN);
        d_wsc2[k*32+p] = make_float2(w_sc[k*64+p]*ss0, w_sc[k*64+p+32]*ss1);
    }
    // biases
    if (t0 < 64){
        int p = t0;
        float s = g_nb[p]*rsqrtf(v_nb[p]+EPSBN);
        d_bnb[p] = (b_nb[p]-m_nb[p])*s + be_nb[p];
        float so = g_out[p]*rsqrtf(v_out[p]+EPSBN);
        d_boutN[p] = (b_out[p]-m_out[p])*so + be_out[p];
    }
    if (t0 < 32){
        int p = t0;
        float sr = g_raw[p]*rsqrtf(v_raw[p]+EPSBN);
        d_braw[p] = (b_raw[p]-m_raw[p])*sr + be_raw[p];
        float ss0 = g_sc[p]*rsqrtf(v_sc[p]+EPSBN);
        float ss1 = g_sc[p+32]*rsqrtf(v_sc[p+32]+EPSBN);
        d_bsc2[p] = make_float2((b_sc[p]-m_sc[p])*ss0+be_sc[p],
                                (b_sc[p+32]-m_sc[p+32])*ss1+be_sc[p+32]);
    }
}

// ---- Kernel 1: G = feature @ W_nb_top', SC = feature @ w_sc' + b_sc'. ----
__global__ void __launch_bounds__(256) g_kernel(const float* __restrict__ feature)
{
    __shared__ float2 swG[32*32];
    __shared__ float2 swS[32*32];
    for (int i = threadIdx.x; i < 1024; i += 256){ swG[i] = d_wnbt2[i]; swS[i] = d_wsc2[i]; }
    __syncthreads();
    const int gidx = blockIdx.x*256 + threadIdx.x;
    const int pt = gidx >> 5, lane = gidx & 31;
    const float f = feature[pt*32 + lane];
    F2U accg; accg.f = make_float2(0.f, 0.f);
    F2U accs; accs.f = d_bsc2[lane];
    #pragma unroll
    for (int k=0;k<32;k++){
        unsigned long long ad = packdup(__shfl_sync(0xffffffffu, f, k));
        F2U wg; wg.f = swG[k*32+lane];
        F2U ws; ws.f = swS[k*32+lane];
        ffma2(accg.u, ad, wg.u);
        ffma2(accs.u, ad, ws.u);
    }
    d_G[(size_t)pt*64 + lane]       = accg.f.x;
    d_G[(size_t)pt*64 + lane + 32]  = accg.f.y;
    d_SC[(size_t)pt*64 + lane]      = accs.f.x;
    d_SC[(size_t)pt*64 + lane + 32] = accs.f.y;
}

// ---- Kernel 2: fused main. One warp/point; bf16 3-split m16n8k16 GEMM chain. ----
// mma lane roles: g = lane>>2 (0..7), t = lane&3 (0..3).
__global__ void __launch_bounds__(128, 4) main_kernel(
    const float* __restrict__ raw,
    const int*   __restrict__ nbr)
{
    const int tid = threadIdx.x, lane = tid & 31, w = tid >> 5;
    const int g = lane >> 2, t = lane & 3;

    const int pt = blockIdx.x*4 + w;
    const int bbase = (pt >> 16) << 16;     // batch offset (N=65536)

    int idxv = 0;
    if (lane < 16) idxv = nbr[pt*16 + lane];
    const int jr0 = __shfl_sync(0xffffffffu, idxv, g);
    const int jr1 = __shfl_sync(0xffffffffu, idxv, g+8);

    // ---- raw A-frags straight from gmem ----
    const float2* raw2 = (const float2*)raw + (size_t)pt*80;
    uint32_t ah[4], al[4];
    {
        float2 p0 = raw2[g*5 + t];
        float2 p1 = raw2[(g+8)*5 + t];
        float2 p2 = (t==0) ? raw2[g*5 + 4]     : make_float2(0.f,0.f);
        float2 p3 = (t==0) ? raw2[(g+8)*5 + 4] : make_float2(0.f,0.f);
        split_pair(p0.x, p0.y, ah[0], al[0]);
        split_pair(p1.x, p1.y, ah[1], al[1]);
        split_pair(p2.x, p2.y, ah[2], al[2]);
        split_pair(p3.x, p3.y, ah[3], al[3]);
    }

    // ---- raw mlp: rmD(16x32) = raw(16x16) @ Wraw + braw; lrelu in place ----
    float rmD[4][4];
    #pragma unroll
    for (int nt=0;nt<4;nt++){
        float2 b = *(const float2*)&d_braw[nt*8 + 2*t];
        rmD[nt][0]=b.x; rmD[nt][1]=b.y; rmD[nt][2]=b.x; rmD[nt][3]=b.y;
    }
    #pragma unroll
    for (int nt=0;nt<4;nt++)
        mma3(rmD[nt], ah, al, d_fragRaw[nt*32 + lane]);
    #pragma unroll
    for (int nt=0;nt<4;nt++)
        #pragma unroll
        for (int i=0;i<4;i++) rmD[nt][i] = lrelu(rmD[nt][i]);

    // ---- prefetch G rows (L2 latency overlaps the R-GEMM mma block below) ----
    float2 ga[8], gb[8];
    {
        const float* G0 = d_G + (size_t)(bbase + jr0)*64;
        const float* G1 = d_G + (size_t)(bbase + jr1)*64;
        #pragma unroll
        for (int nt=0;nt<8;nt++){
            ga[nt] = *(const float2*)&G0[nt*8 + 2*t];
            gb[nt] = *(const float2*)&G1[nt*8 + 2*t];
        }
    }

    // ---- R-GEMM: hv(16x64) = rm(16x32) @ W_nbb + bnb ----
    float hv[8][4];
    #pragma unroll
    for (int nt=0;nt<8;nt++){
        float2 b = *(const float2*)&d_bnb[nt*8 + 2*t];
        hv[nt][0]=b.x; hv[nt][1]=b.y; hv[nt][2]=b.x; hv[nt][3]=b.y;
    }
    #pragma unroll
    for (int kc=0;kc<2;kc++){
        dfrags_to_afrags(rmD[2*kc], rmD[2*kc+1], ah, al);
        #pragma unroll
        for (int nt=0;nt<8;nt++)
            mma3(hv[nt], ah, al, d_fragR[(kc*8+nt)*32 + lane]);
    }

    // ---- h = lrelu(G + hv), in place ----
    #pragma unroll
    for (int nt=0;nt<8;nt++){
        hv[nt][0] = lrelu(hv[nt][0] + ga[nt].x);
        hv[nt][1] = lrelu(hv[nt][1] + ga[nt].y);
        hv[nt][2] = lrelu(hv[nt][2] + gb[nt].x);
        hv[nt][3] = lrelu(hv[nt][3] + gb[nt].y);
    }

    // ---- pre-split A-frags for the s-GEMM (all 4 kc) ----
    uint32_t sah[4][4], sal[4][4];
    #pragma unroll
    for (int kc=0;kc<4;kc++)
        dfrags_to_afrags(hv[2*kc], hv[2*kc+1], sah[kc], sal[kc]);

    // ---- s-GEMM per nt + immediate softmax partials (no max shift; |s| small) ----
    float Kd[8], Kn[8];
    const bool gb0 = (lane & 4) != 0;
    #pragma unroll
    for (int nt=0;nt<8;nt++){
        float sd[4] = {0.f, 0.f, 0.f, 0.f};
        #pragma unroll
        for (int kc=0;kc<4;kc++)
            mma3(sd, sah[kc], sal[kc], d_fragS[(kc*8+nt)*32 + lane]);
        float e0=__expf(sd[0]), e1=__expf(sd[1]);
        float e2=__expf(sd[2]), e3=__expf(sd[3]);
        float den0 = e0+e2, num0 = fmaf(e0, hv[nt][0], e2*hv[nt][2]);
        float den1 = e1+e3, num1 = fmaf(e1, hv[nt][1], e3*hv[nt][3]);
        float sdd = gb0 ? den0 : den1;
        float snn = gb0 ? num0 : num1;
        float rd = __shfl_xor_sync(0xffffffffu, sdd, 4);
        float rn = __shfl_xor_sync(0xffffffffu, snn, 4);
        Kd[nt] = (gb0 ? den1 : den0) + rd;
        Kn[nt] = (gb0 ? num1 : num0) + rn;
    }
    const bool gb1 = (lane & 8) != 0;
    float Ld[4], Ln[4];
    #pragma unroll
    for (int j=0;j<4;j++){
        float sd = gb1 ? Kd[j] : Kd[j+4];
        float sn = gb1 ? Kn[j] : Kn[j+4];
        float rd = __shfl_xor_sync(0xffffffffu, sd, 8);
        float rn = __shfl_xor_sync(0xffffffffu, sn, 8);
        Ld[j] = (gb1 ? Kd[j+4] : Kd[j]) + rd;
        Ln[j] = (gb1 ? Kn[j+4] : Kn[j]) + rn;
    }
    const bool gb2 = (lane & 16) != 0;
    #pragma unroll
    for (int j=0;j<2;j++){
        float sd = gb2 ? Ld[j] : Ld[j+2];
        float sn = gb2 ? Ln[j] : Ln[j+2];
        float rd = __shfl_xor_sync(0xffffffffu, sd, 16);
        float rn = __shfl_xor_sync(0xffffffffu, sn, 16);
        float md = (gb2 ? Ld[j+2] : Ld[j]) + rd;
        float mn = (gb2 ? Ln[j+2] : Ln[j]) + rn;
        int nt = j + (gb2 ? 2 : 0) + (gb1 ? 4 : 0);
        int c  = nt*8 + 2*t + (gb0 ? 1 : 0);
        d_P[(size_t)pt*64 + c] = __fdividef(mn, md);
    }
}

// ---- Kernel 3: out = lrelu(SC + pooled @ w_out' + b_out'). 16 points/warp. ----
__global__ void __launch_bounds__(256) out_kernel(float* __restrict__ outp)
{
    const int tid = threadIdx.x, lane = tid & 31, w = tid >> 5;
    const int g = lane >> 2, t = lane & 3;
    const int ptb = (blockIdx.x*8 + w)*16;

    const float2* P0 = (const float2*)(d_P + (size_t)(ptb+g)*64);
    const float2* P1 = (const float2*)(d_P + (size_t)(ptb+g+8)*64);

    float D[8][4];
    #pragma unroll
    for (int nt=0;nt<8;nt++){
        float2 b = *(const float2*)&d_boutN[nt*8 + 2*t];
        D[nt][0]=b.x; D[nt][1]=b.y; D[nt][2]=b.x; D[nt][3]=b.y;
    }
    uint32_t ah[4], al[4];
    #pragma unroll
    for (int kc=0;kc<4;kc++){
        float2 p0 = P0[kc*8 + t];
        float2 p1 = P1[kc*8 + t];
        float2 p2 = P0[kc*8 + t + 4];
        float2 p3 = P1[kc*8 + t + 4];
        split_pair(p0.x, p0.y, ah[0], al[0]);
        split_pair(p1.x, p1.y, ah[1], al[1]);
        split_pair(p2.x, p2.y, ah[2], al[2]);
        split_pair(p3.x, p3.y, ah[3], al[3]);
        #pragma unroll
        for (int nt=0;nt<8;nt++)
            mma3(D[nt], ah, al, d_fragOut[(kc*8+nt)*32 + lane]);
    }
    const float* S0 = d_SC + (size_t)(ptb+g)*64;
    const float* S1 = d_SC + (size_t)(ptb+g+8)*64;
    #pragma unroll
    for (int nt=0;nt<8;nt++){
        float2 s0 = *(const float2*)&S0[nt*8 + 2*t];
        float2 s1 = *(const float2*)&S1[nt*8 + 2*t];
        *(float2*)&outp[(size_t)(ptb+g)*64   + nt*8 + 2*t] =
            make_float2(lrelu(D[nt][0] + s0.x), lrelu(D[nt][1] + s0.y));
        *(float2*)&outp[(size_t)(ptb+g+8)*64 + nt*8 + 2*t] =
            make_float2(lrelu(D[nt][2] + s1.x), lrelu(D[nt][3] + s1.y));
    }
}

extern "C" void kernel_launch(void* const* d_in, const int* in_sizes, int n_in,
                              void* d_out, int out_size)
{
    const float* feature = (const float*)d_in[0];
    const float* raw     = (const float*)d_in[1];
    const int*   nbr     = (const int*)  d_in[2];

    fold_kernel<<<1, 1024>>>(
        (const float*)d_in[3],  (const float*)d_in[4],  (const float*)d_in[5],
        (const float*)d_in[6],  (const float*)d_in[7],  (const float*)d_in[8],
        (const float*)d_in[9],  (const float*)d_in[10], (const float*)d_in[11],
        (const float*)d_in[12], (const float*)d_in[13], (const float*)d_in[14],
        (const float*)d_in[15],
        (const float*)d_in[16], (const float*)d_in[17], (const float*)d_in[18],
        (const float*)d_in[19], (const float*)d_in[20], (const float*)d_in[21],
        (const float*)d_in[22], (const float*)d_in[23], (const float*)d_in[24],
        (const float*)d_in[25], (const float*)d_in[26], (const float*)d_in[27]);

    g_kernel<<<(NPTS*32)/256, 256>>>(feature);

    main_kernel<<<NPTS/4, 128>>>(raw, nbr);

    out_kernel<<<NPTS/(16*8), 256>>>((float*)d_out);
}

// round 15
// speedup vs baseline: 4.3440x; 1.1477x over previous
#include <cuda_runtime.h>
#include <cstdint>

#define NPTS   131072          // B*N = 2*65536
#define EPSBN  1e-5f

// ---- fragment-ordered weight tables + folded params (device globals) ----
__device__ __align__(16) uint4  d_fragRaw[4*32];     // raw mlp bf16 3-split: K=16(pad of 10), N=32
__device__ __align__(16) uint2  d_fragR2[16*32];     // W_nb bottom fp16: K=32 (2 kc), N=64 (8 nt)
__device__ __align__(16) uint2  d_fragS2[32*32];     // w_attn fp16: K=64 (4 kc), N=64 (8 nt)
__device__ __align__(16) uint4  d_fragOut[32*32];    // w_out folded bf16 3-split
__device__ __align__(16) float  d_braw[32];
__device__ __align__(16) float  d_bnb[64];
__device__ __align__(16) float  d_boutN[64];
__device__ __align__(16) float2 d_wnbt2[32*32];      // W_nb top (for G), pair (c, c+32)
__device__ __align__(16) float2 d_wsc2[32*32];
__device__ __align__(16) float2 d_bsc2[32];
__device__ __align__(16) float  d_G[(size_t)NPTS*64];  // feature @ W_nb_top'   (~33.5MB)
__device__ __align__(16) float  d_SC[(size_t)NPTS*64]; // feature @ w_sc' + b   (~33.5MB)
__device__ __align__(16) float  d_P[(size_t)NPTS*64];  // pooled                (~33.5MB)

union F2U { float2 f; unsigned long long u; };
__device__ __forceinline__ unsigned long long packdup(float a){
    unsigned long long r; asm("mov.b64 %0, {%1, %1};" : "=l"(r) : "f"(a)); return r;
}
__device__ __forceinline__ void ffma2(unsigned long long& d, unsigned long long a, unsigned long long b){
    asm("fma.rn.f32x2 %0, %1, %2, %0;" : "+l"(d) : "l"(a), "l"(b));
}
__device__ __forceinline__ float lrelu(float x){ return fmaxf(x, 0.2f*x); }

// ---- bf16 3-split helpers (raw mlp + out kernel) ----
__device__ __forceinline__ uint32_t pack_bf16x2(float lo, float hi){
    uint32_t r; asm("cvt.rn.bf16x2.f32 %0, %1, %2;" : "=r"(r) : "f"(hi), "f"(lo)); return r;
}
__device__ __forceinline__ void split_pair(float x0, float x1, uint32_t& ah, uint32_t& al){
    ah = pack_bf16x2(x0, x1);
    float h0 = __uint_as_float(ah << 16);
    float h1 = __uint_as_float(ah & 0xFFFF0000u);
    al = pack_bf16x2(x0 - h0, x1 - h1);
}
__device__ __forceinline__ void mma_bf16(float* d, const uint32_t* a, uint32_t b0, uint32_t b1){
    asm volatile("mma.sync.aligned.m16n8k16.row.col.f32.bf16.bf16.f32 "
        "{%0,%1,%2,%3},{%4,%5,%6,%7},{%8,%9},{%0,%1,%2,%3};"
        : "+f"(d[0]),"+f"(d[1]),"+f"(d[2]),"+f"(d[3])
        : "r"(a[0]),"r"(a[1]),"r"(a[2]),"r"(a[3]),"r"(b0),"r"(b1));
}
__device__ __forceinline__ void mma3(float* d, const uint32_t* ah, const uint32_t* al, uint4 b){
    mma_bf16(d, ah, b.x, b.y);
    mma_bf16(d, al, b.x, b.y);
    mma_bf16(d, ah, b.z, b.w);
}

// ---- fp16 2-split helpers (R + s GEMMs): A = Ah+Al (fp16), B = fp16 ----
__device__ __forceinline__ uint32_t pack_f16x2(float lo, float hi){
    uint32_t r; asm("cvt.rn.f16x2.f32 %0, %1, %2;" : "=r"(r) : "f"(hi), "f"(lo)); return r;
}
__device__ __forceinline__ void split_pair_f16(float x0, float x1, uint32_t& ah, uint32_t& al){
    ah = pack_f16x2(x0, x1);
    float h0, h1;
    asm("{.reg .f16 lo, hi;\n\t mov.b32 {lo, hi}, %2;\n\t"
        "cvt.f32.f16 %0, lo;\n\t cvt.f32.f16 %1, hi;}" : "=f"(h0), "=f"(h1) : "r"(ah));
    al = pack_f16x2(x0 - h0, x1 - h1);
}
__device__ __forceinline__ void mma_f16(float* d, const uint32_t* a, uint32_t b0, uint32_t b1){
    asm volatile("mma.sync.aligned.m16n8k16.row.col.f32.f16.f16.f32 "
        "{%0,%1,%2,%3},{%4,%5,%6,%7},{%8,%9},{%0,%1,%2,%3};"
        : "+f"(d[0]),"+f"(d[1]),"+f"(d[2]),"+f"(d[3])
        : "r"(a[0]),"r"(a[1]),"r"(a[2]),"r"(a[3]),"r"(b0),"r"(b1));
}
__device__ __forceinline__ void mma2(float* d, const uint32_t* ah, const uint32_t* al, uint2 b){
    mma_f16(d, ah, b.x, b.y);
    mma_f16(d, al, b.x, b.y);
}
__device__ __forceinline__ void dfrags_to_afrags_f16(const float* dA, const float* dB,
                                                     uint32_t* ah, uint32_t* al){
    split_pair_f16(dA[0], dA[1], ah[0], al[0]);
    split_pair_f16(dA[2], dA[3], ah[1], al[1]);
    split_pair_f16(dB[0], dB[1], ah[2], al[2]);
    split_pair_f16(dB[2], dB[3], ah[3], al[3]);
}
__device__ __forceinline__ void dfrags_to_afrags(const float* dA, const float* dB,
                                                 uint32_t* ah, uint32_t* al){
    split_pair(dA[0], dA[1], ah[0], al[0]);
    split_pair(dA[2], dA[3], ah[1], al[1]);
    split_pair(dB[0], dB[1], ah[2], al[2]);
    split_pair(dB[2], dB[3], ah[3], al[3]);
}

// ---- Kernel 0: fold BN into weights; build fragment tables. ----
__global__ void __launch_bounds__(1024) fold_kernel(
    const float* w_raw, const float* b_raw, const float* g_raw, const float* be_raw,
    const float* m_raw, const float* v_raw,
    const float* w_nb,  const float* b_nb,  const float* g_nb,  const float* be_nb,
    const float* m_nb,  const float* v_nb,  const float* w_attn,
    const float* w_out, const float* b_out, const float* g_out, const float* be_out,
    const float* m_out, const float* v_out,
    const float* w_sc,  const float* b_sc,  const float* g_sc,  const float* be_sc,
    const float* m_sc,  const float* v_sc)
{
    const int t0 = threadIdx.x;
    const int lane = t0 & 31, gg = lane >> 2, tt = lane & 3;

    // fragRaw (bf16 3-split): 128 entries (nt 0..3); k>=10 -> 0
    if (t0 < 128){
        int nt = t0 >> 5, n = nt*8 + gg;
        float sn = g_raw[n]*rsqrtf(v_raw[n]+EPSBN);
        int k0 = 2*tt, k2 = 2*tt + 8;
        float w0 = w_raw[k0*32+n]*sn;
        float w1 = w_raw[(k0+1)*32+n]*sn;
        float w2 = (k2   < 10) ? w_raw[k2*32+n]*sn     : 0.f;
        float w3 = (k2+1 < 10) ? w_raw[(k2+1)*32+n]*sn : 0.f;
        uint32_t h0,l0,h1,l1; split_pair(w0,w1,h0,l0); split_pair(w2,w3,h1,l1);
        d_fragRaw[t0] = make_uint4(h0,h1,l0,l1);
    }
    // fragR2 (fp16): 512 entries (entry = kc*8+nt)
    if (t0 < 512){
        int entry = t0 >> 5, nt = entry & 7, kc = entry >> 3, n = nt*8 + gg;
        float sn = g_nb[n]*rsqrtf(v_nb[n]+EPSBN);
        int k0 = kc*16 + 2*tt;
        float w0 = w_nb[(32+k0)*64+n]*sn,   w1 = w_nb[(32+k0+1)*64+n]*sn;
        float w2 = w_nb[(32+k0+8)*64+n]*sn, w3 = w_nb[(32+k0+9)*64+n]*sn;
        d_fragR2[t0] = make_uint2(pack_f16x2(w0,w1), pack_f16x2(w2,w3));
    }
    // fragS2 (fp16): 1024 entries (entry = kc*8+nt, kc 0..3)
    {
        int entry = t0 >> 5, nt = entry & 7, kc = entry >> 3, n = nt*8 + gg;
        int k0 = kc*16 + 2*tt;
        float w0 = w_attn[k0*64+n],     w1 = w_attn[(k0+1)*64+n];
        float w2 = w_attn[(k0+8)*64+n], w3 = w_attn[(k0+9)*64+n];
        d_fragS2[t0] = make_uint2(pack_f16x2(w0,w1), pack_f16x2(w2,w3));
    }
    // fragOut (bf16 3-split): 1024 entries, folded w_out
    {
        int entry = t0 >> 5, nt = entry & 7, kc = entry >> 3, n = nt*8 + gg;
        float sn = g_out[n]*rsqrtf(v_out[n]+EPSBN);
        int k0 = kc*16 + 2*tt;
        float w0 = w_out[k0*64+n]*sn,     w1 = w_out[(k0+1)*64+n]*sn;
        float w2 = w_out[(k0+8)*64+n]*sn, w3 = w_out[(k0+9)*64+n]*sn;
        uint32_t h0,l0,h1,l1; split_pair(w0,w1,h0,l0); split_pair(w2,w3,h1,l1);
        d_fragOut[t0] = make_uint4(h0,h1,l0,l1);
    }
    // W_nb top (paired) + w_sc (paired)
    {
        int k = t0/32, p = t0%32;
        float s0 = g_nb[p]*rsqrtf(v_nb[p]+EPSBN);
        float s1 = g_nb[p+32]*rsqrtf(v_nb[p+32]+EPSBN);
        d_wnbt2[k*32+p] = make_float2(w_nb[k*64+p]*s0, w_nb[k*64+p+32]*s1);
        float ss0 = g_sc[p]*rsqrtf(v_sc[p]+EPSBN);
        float ss1 = g_sc[p+32]*rsqrtf(v_sc[p+32]+EPSBN);
        d_wsc2[k*32+p] = make_float2(w_sc[k*64+p]*ss0, w_sc[k*64+p+32]*ss1);
    }
    // biases
    if (t0 < 64){
        int p = t0;
        float s = g_nb[p]*rsqrtf(v_nb[p]+EPSBN);
        d_bnb[p] = (b_nb[p]-m_nb[p])*s + be_nb[p];
        float so = g_out[p]*rsqrtf(v_out[p]+EPSBN);
        d_boutN[p] = (b_out[p]-m_out[p])*so + be_out[p];
    }
    if (t0 < 32){
        int p = t0;
        float sr = g_raw[p]*rsqrtf(v_raw[p]+EPSBN);
        d_braw[p] = (b_raw[p]-m_raw[p])*sr + be_raw[p];
        float ss0 = g_sc[p]*rsqrtf(v_sc[p]+EPSBN);
        float ss1 = g_sc[p+32]*rsqrtf(v_sc[p+32]+EPSBN);
        d_bsc2[p] = make_float2((b_sc[p]-m_sc[p])*ss0+be_sc[p],
                                (b_sc[p+32]-m_sc[p+32])*ss1+be_sc[p+32]);
    }
}

// ---- Kernel 1: G = feature @ W_nb_top', SC = feature @ w_sc' + b_sc'. ----
__global__ void __launch_bounds__(256) g_kernel(const float* __restrict__ feature)
{
    __shared__ float2 swG[32*32];
    __shared__ float2 swS[32*32];
    for (int i = threadIdx.x; i < 1024; i += 256){ swG[i] = d_wnbt2[i]; swS[i] = d_wsc2[i]; }
    __syncthreads();
    const int gidx = blockIdx.x*256 + threadIdx.x;
    const int pt = gidx >> 5, lane = gidx & 31;
    const float f = feature[pt*32 + lane];
    F2U accg; accg.f = make_float2(0.f, 0.f);
    F2U accs; accs.f = d_bsc2[lane];
    #pragma unroll
    for (int k=0;k<32;k++){
        unsigned long long ad = packdup(__shfl_sync(0xffffffffu, f, k));
        F2U wg; wg.f = swG[k*32+lane];
        F2U ws; ws.f = swS[k*32+lane];
        ffma2(accg.u, ad, wg.u);
        ffma2(accs.u, ad, ws.u);
    }
    d_G[(size_t)pt*64 + lane]       = accg.f.x;
    d_G[(size_t)pt*64 + lane + 32]  = accg.f.y;
    d_SC[(size_t)pt*64 + lane]      = accs.f.x;
    d_SC[(size_t)pt*64 + lane + 32] = accs.f.y;
}

// ---- Kernel 2: fused main. One warp/point; bf16 raw-mlp + fp16 2-split R/s. ----
__global__ void __launch_bounds__(128, 4) main_kernel(
    const float* __restrict__ raw,
    const int*   __restrict__ nbr)
{
    const int tid = threadIdx.x, lane = tid & 31, w = tid >> 5;
    const int g = lane >> 2, t = lane & 3;

    const int pt = blockIdx.x*4 + w;
    const int bbase = (pt >> 16) << 16;     // batch offset (N=65536)

    int idxv = 0;
    if (lane < 16) idxv = nbr[pt*16 + lane];
    const int jr0 = __shfl_sync(0xffffffffu, idxv, g);
    const int jr1 = __shfl_sync(0xffffffffu, idxv, g+8);

    // ---- raw A-frags straight from gmem (bf16 3-split) ----
    const float2* raw2 = (const float2*)raw + (size_t)pt*80;
    uint32_t ah[4], al[4];
    {
        float2 p0 = raw2[g*5 + t];
        float2 p1 = raw2[(g+8)*5 + t];
        float2 p2 = (t==0) ? raw2[g*5 + 4]     : make_float2(0.f,0.f);
        float2 p3 = (t==0) ? raw2[(g+8)*5 + 4] : make_float2(0.f,0.f);
        split_pair(p0.x, p0.y, ah[0], al[0]);
        split_pair(p1.x, p1.y, ah[1], al[1]);
        split_pair(p2.x, p2.y, ah[2], al[2]);
        split_pair(p3.x, p3.y, ah[3], al[3]);
    }

    // ---- raw mlp: rmD(16x32) = raw(16x16) @ Wraw + braw; lrelu in place ----
    float rmD[4][4];
    #pragma unroll
    for (int nt=0;nt<4;nt++){
        float2 b = *(const float2*)&d_braw[nt*8 + 2*t];
        rmD[nt][0]=b.x; rmD[nt][1]=b.y; rmD[nt][2]=b.x; rmD[nt][3]=b.y;
    }
    #pragma unroll
    for (int nt=0;nt<4;nt++)
        mma3(rmD[nt], ah, al, d_fragRaw[nt*32 + lane]);
    #pragma unroll
    for (int nt=0;nt<4;nt++)
        #pragma unroll
        for (int i=0;i<4;i++) rmD[nt][i] = lrelu(rmD[nt][i]);

    // ---- prefetch G rows (L2 latency overlaps the R-GEMM mma block below) ----
    float2 ga[8], gb[8];
    {
        const float* G0 = d_G + (size_t)(bbase + jr0)*64;
        const float* G1 = d_G + (size_t)(bbase + jr1)*64;
        #pragma unroll
        for (int nt=0;nt<8;nt++){
            ga[nt] = *(const float2*)&G0[nt*8 + 2*t];
            gb[nt] = *(const float2*)&G1[nt*8 + 2*t];
        }
    }

    // ---- R-GEMM (fp16 2-split): hv(16x64) = rm(16x32) @ W_nbb + bnb ----
    float hv[8][4];
    #pragma unroll
    for (int nt=0;nt<8;nt++){
        float2 b = *(const float2*)&d_bnb[nt*8 + 2*t];
        hv[nt][0]=b.x; hv[nt][1]=b.y; hv[nt][2]=b.x; hv[nt][3]=b.y;
    }
    #pragma unroll
    for (int kc=0;kc<2;kc++){
        dfrags_to_afrags_f16(rmD[2*kc], rmD[2*kc+1], ah, al);
        #pragma unroll
        for (int nt=0;nt<8;nt++)
            mma2(hv[nt], ah, al, d_fragR2[(kc*8+nt)*32 + lane]);
    }

    // ---- h = lrelu(G + hv), in place ----
    #pragma unroll
    for (int nt=0;nt<8;nt++){
        hv[nt][0] = lrelu(hv[nt][0] + ga[nt].x);
        hv[nt][1] = lrelu(hv[nt][1] + ga[nt].y);
        hv[nt][2] = lrelu(hv[nt][2] + gb[nt].x);
        hv[nt][3] = lrelu(hv[nt][3] + gb[nt].y);
    }

    // ---- pre-split A-frags for the s-GEMM (all 4 kc, fp16) ----
    uint32_t sah[4][4], sal[4][4];
    #pragma unroll
    for (int kc=0;kc<4;kc++)
        dfrags_to_afrags_f16(hv[2*kc], hv[2*kc+1], sah[kc], sal[kc]);

    // ---- s-GEMM per nt (fp16 2-split) + immediate softmax partials ----
    float Kd[8], Kn[8];
    const bool gb0 = (lane & 4) != 0;
    #pragma unroll
    for (int nt=0;nt<8;nt++){
        float sd[4] = {0.f, 0.f, 0.f, 0.f};
        #pragma unroll
        for (int kc=0;kc<4;kc++)
            mma2(sd, sah[kc], sal[kc], d_fragS2[(kc*8+nt)*32 + lane]);
        float e0=__expf(sd[0]), e1=__expf(sd[1]);
        float e2=__expf(sd[2]), e3=__expf(sd[3]);
        float den0 = e0+e2, num0 = fmaf(e0, hv[nt][0], e2*hv[nt][2]);
        float den1 = e1+e3, num1 = fmaf(e1, hv[nt][1], e3*hv[nt][3]);
        float sdd = gb0 ? den0 : den1;
        float snn = gb0 ? num0 : num1;
        float rd = __shfl_xor_sync(0xffffffffu, sdd, 4);
        float rn = __shfl_xor_sync(0xffffffffu, snn, 4);
        Kd[nt] = (gb0 ? den1 : den0) + rd;
        Kn[nt] = (gb0 ? num1 : num0) + rn;
    }
    const bool gb1 = (lane & 8) != 0;
    float Ld[4], Ln[4];
    #pragma unroll
    for (int j=0;j<4;j++){
        float sd = gb1 ? Kd[j] : Kd[j+4];
        float sn = gb1 ? Kn[j] : Kn[j+4];
        float rd = __shfl_xor_sync(0xffffffffu, sd, 8);
        float rn = __shfl_xor_sync(0xffffffffu, sn, 8);
        Ld[j] = (gb1 ? Kd[j+4] : Kd[j]) + rd;
        Ln[j] = (gb1 ? Kn[j+4] : Kn[j]) + rn;
    }
    const bool gb2 = (lane & 16) != 0;
    #pragma unroll
    for (int j=0;j<2;j++){
        float sd = gb2 ? Ld[j] : Ld[j+2];
        float sn = gb2 ? Ln[j] : Ln[j+2];
        float rd = __shfl_xor_sync(0xffffffffu, sd, 16);
        float rn = __shfl_xor_sync(0xffffffffu, sn, 16);
        float md = (gb2 ? Ld[j+2] : Ld[j]) + rd;
        float mn = (gb2 ? Ln[j+2] : Ln[j]) + rn;
        int nt = j + (gb2 ? 2 : 0) + (gb1 ? 4 : 0);
        int c  = nt*8 + 2*t + (gb0 ? 1 : 0);
        d_P[(size_t)pt*64 + c] = __fdividef(mn, md);
    }
}

// ---- Kernel 3: out = lrelu(SC + pooled @ w_out' + b_out'). N-split: 4 nt/warp. ----
__global__ void __launch_bounds__(256) out_kernel(float* __restrict__ outp)
{
    const int tid = threadIdx.x, lane = tid & 31, w = tid >> 5;
    const int g = lane >> 2, t = lane & 3;
    const int par = blockIdx.x & 1;                 // N half: nt in [4*par, 4*par+4)
    const int ptb = ((blockIdx.x >> 1)*8 + w)*16;

    const float2* P0 = (const float2*)(d_P + (size_t)(ptb+g)*64);
    const float2* P1 = (const float2*)(d_P + (size_t)(ptb+g+8)*64);

    float D[4][4];
    #pragma unroll
    for (int nt=0;nt<4;nt++){
        float2 b = *(const float2*)&d_boutN[(nt+4*par)*8 + 2*t];
        D[nt][0]=b.x; D[nt][1]=b.y; D[nt][2]=b.x; D[nt][3]=b.y;
    }
    uint32_t ah[4], al[4];
    #pragma unroll
    for (int kc=0;kc<4;kc++){
        float2 p0 = P0[kc*8 + t];
        float2 p1 = P1[kc*8 + t];
        float2 p2 = P0[kc*8 + t + 4];
        float2 p3 = P1[kc*8 + t + 4];
        split_pair(p0.x, p0.y, ah[0], al[0]);
        split_pair(p1.x, p1.y, ah[1], al[1]);
        split_pair(p2.x, p2.y, ah[2], al[2]);
        split_pair(p3.x, p3.y, ah[3], al[3]);
        #pragma unroll
        for (int nt=0;nt<4;nt++)
            mma3(D[nt], ah, al, d_fragOut[(kc*8 + nt + 4*par)*32 + lane]);
    }
    const float* S0 = d_SC + (size_t)(ptb+g)*64;
    const float* S1 = d_SC + (size_t)(ptb+g+8)*64;
    #pragma unroll
    for (int nt=0;nt<4;nt++){
        int c = (nt+4*par)*8 + 2*t;
        float2 s0 = *(const float2*)&S0[c];
        float2 s1 = *(const float2*)&S1[c];
        *(float2*)&outp[(size_t)(ptb+g)*64   + c] =
            make_float2(lrelu(D[nt][0] + s0.x), lrelu(D[nt][1] + s0.y));
        *(float2*)&outp[(size_t)(ptb+g+8)*64 + c] =
            make_float2(lrelu(D[nt][2] + s1.x), lrelu(D[nt][3] + s1.y));
    }
}

extern "C" void kernel_launch(void* const* d_in, const int* in_sizes, int n_in,
                              void* d_out, int out_size)
{
    const float* feature = (const float*)d_in[0];
    const float* raw     = (const float*)d_in[1];
    const int*   nbr     = (const int*)  d_in[2];

    fold_kernel<<<1, 1024>>>(
        (const float*)d_in[3],  (const float*)d_in[4],  (const float*)d_in[5],
        (const float*)d_in[6],  (const float*)d_in[7],  (const float*)d_in[8],
        (const float*)d_in[9],  (const float*)d_in[10], (const float*)d_in[11],
        (const float*)d_in[12], (const float*)d_in[13], (const float*)d_in[14],
        (const float*)d_in[15],
        (const float*)d_in[16], (const float*)d_in[17], (const float*)d_in[18],
        (const float*)d_in[19], (const float*)d_in[20], (const float*)d_in[21],
        (const float*)d_in[22], (const float*)d_in[23], (const float*)d_in[24],
        (const float*)d_in[25], (const float*)d_in[26], (const float*)d_in[27]);

    g_kernel<<<(NPTS*32)/256, 256>>>(feature);

    main_kernel<<<NPTS/4, 128>>>(raw, nbr);

    out_kernel<<<NPTS/(16*8)*2, 256>>>((float*)d_out);
}

// round 16
// speedup vs baseline: 5.5619x; 1.2804x over previous
#include <cuda_runtime.h>
#include <cstdint>

#define NPTS   131072          // B*N = 2*65536
#define EPSBN  1e-5f
#define LOG2E  1.4426950408889634f

// ---- fragment-ordered weight tables + folded params (device globals) ----
__device__ __align__(16) uint4  d_fragRaw[4*32];     // raw mlp bf16 3-split: K=16(pad of 10), N=32
__device__ __align__(16) uint2  d_fragR2[16*32];     // W_nb bottom fp16: K=32 (2 kc), N=64 (8 nt)
__device__ __align__(16) uint2  d_fragS2[32*32];     // w_attn*log2e fp16: K=64 (4 kc), N=64 (8 nt)
__device__ __align__(16) uint4  d_fragOut[32*32];    // w_out folded bf16 3-split
__device__ __align__(16) uint4  d_fragGt[16*32];     // W_nb top folded bf16 3-split: K=32, N=64
__device__ __align__(16) uint4  d_fragSc[16*32];     // w_sc folded bf16 3-split: K=32, N=64
__device__ __align__(16) float  d_braw[32];
__device__ __align__(16) float  d_bnb[64];
__device__ __align__(16) float  d_boutN[64];
__device__ __align__(16) float  d_bscN[64];
__device__ __align__(16) float  d_G[(size_t)NPTS*64];  // feature @ W_nb_top' + bnb (~33.5MB)
__device__ __align__(16) float  d_SC[(size_t)NPTS*64]; // feature @ w_sc' + b_sc'   (~33.5MB)
__device__ __align__(16) float  d_P[(size_t)NPTS*64];  // pooled                    (~33.5MB)

__device__ __forceinline__ float lrelu(float x){ return fmaxf(x, 0.2f*x); }

// ---- bf16 3-split helpers ----
__device__ __forceinline__ uint32_t pack_bf16x2(float lo, float hi){
    uint32_t r; asm("cvt.rn.bf16x2.f32 %0, %1, %2;" : "=r"(r) : "f"(hi), "f"(lo)); return r;
}
__device__ __forceinline__ void split_pair(float x0, float x1, uint32_t& ah, uint32_t& al){
    ah = pack_bf16x2(x0, x1);
    float h0 = __uint_as_float(ah << 16);
    float h1 = __uint_as_float(ah & 0xFFFF0000u);
    al = pack_bf16x2(x0 - h0, x1 - h1);
}
__device__ __forceinline__ void mma_bf16(float* d, const uint32_t* a, uint32_t b0, uint32_t b1){
    asm volatile("mma.sync.aligned.m16n8k16.row.col.f32.bf16.bf16.f32 "
        "{%0,%1,%2,%3},{%4,%5,%6,%7},{%8,%9},{%0,%1,%2,%3};"
        : "+f"(d[0]),"+f"(d[1]),"+f"(d[2]),"+f"(d[3])
        : "r"(a[0]),"r"(a[1]),"r"(a[2]),"r"(a[3]),"r"(b0),"r"(b1));
}
__device__ __forceinline__ void mma3(float* d, const uint32_t* ah, const uint32_t* al, uint4 b){
    mma_bf16(d, ah, b.x, b.y);
    mma_bf16(d, al, b.x, b.y);
    mma_bf16(d, ah, b.z, b.w);
}

// ---- fp16 2-split helpers (R + s GEMMs): A = Ah+Al (fp16), B = fp16 ----
__device__ __forceinline__ uint32_t pack_f16x2(float lo, float hi){
    uint32_t r; asm("cvt.rn.f16x2.f32 %0, %1, %2;" : "=r"(r) : "f"(hi), "f"(lo)); return r;
}
__device__ __forceinline__ void split_pair_f16(float x0, float x1, uint32_t& ah, uint32_t& al){
    ah = pack_f16x2(x0, x1);
    float h0, h1;
    asm("{.reg .f16 lo, hi;\n\t mov.b32 {lo, hi}, %2;\n\t"
        "cvt.f32.f16 %0, lo;\n\t cvt.f32.f16 %1, hi;}" : "=f"(h0), "=f"(h1) : "r"(ah));
    al = pack_f16x2(x0 - h0, x1 - h1);
}
__device__ __forceinline__ void mma_f16(float* d, const uint32_t* a, uint32_t b0, uint32_t b1){
    asm volatile("mma.sync.aligned.m16n8k16.row.col.f32.f16.f16.f32 "
        "{%0,%1,%2,%3},{%4,%5,%6,%7},{%8,%9},{%0,%1,%2,%3};"
        : "+f"(d[0]),"+f"(d[1]),"+f"(d[2]),"+f"(d[3])
        : "r"(a[0]),"r"(a[1]),"r"(a[2]),"r"(a[3]),"r"(b0),"r"(b1));
}
__device__ __forceinline__ void mma2(float* d, const uint32_t* ah, const uint32_t* al, uint2 b){
    mma_f16(d, ah, b.x, b.y);
    mma_f16(d, al, b.x, b.y);
}
__device__ __forceinline__ void dfrags_to_afrags_f16(const float* dA, const float* dB,
                                                     uint32_t* ah, uint32_t* al){
    split_pair_f16(dA[0], dA[1], ah[0], al[0]);
    split_pair_f16(dA[2], dA[3], ah[1], al[1]);
    split_pair_f16(dB[0], dB[1], ah[2], al[2]);
    split_pair_f16(dB[2], dB[3], ah[3], al[3]);
}

// ---- Kernel 0: fold BN into weights; build fragment tables. ----
__global__ void __launch_bounds__(1024) fold_kernel(
    const float* w_raw, const float* b_raw, const float* g_raw, const float* be_raw,
    const float* m_raw, const float* v_raw,
    const float* w_nb,  const float* b_nb,  const float* g_nb,  const float* be_nb,
    const float* m_nb,  const float* v_nb,  const float* w_attn,
    const float* w_out, const float* b_out, const float* g_out, const float* be_out,
    const float* m_out, const float* v_out,
    const float* w_sc,  const float* b_sc,  const float* g_sc,  const float* be_sc,
    const float* m_sc,  const float* v_sc)
{
    const int t0 = threadIdx.x;
    const int lane = t0 & 31, gg = lane >> 2, tt = lane & 3;

    // fragRaw (bf16 3-split): 128 entries (nt 0..3); k>=10 -> 0
    if (t0 < 128){
        int nt = t0 >> 5, n = nt*8 + gg;
        float sn = g_raw[n]*rsqrtf(v_raw[n]+EPSBN);
        int k0 = 2*tt, k2 = 2*tt + 8;
        float w0 = w_raw[k0*32+n]*sn;
        float w1 = w_raw[(k0+1)*32+n]*sn;
        float w2 = (k2   < 10) ? w_raw[k2*32+n]*sn     : 0.f;
        float w3 = (k2+1 < 10) ? w_raw[(k2+1)*32+n]*sn : 0.f;
        uint32_t h0,l0,h1,l1; split_pair(w0,w1,h0,l0); split_pair(w2,w3,h1,l1);
        d_fragRaw[t0] = make_uint4(h0,h1,l0,l1);
    }
    // fragR2 (fp16): 512 entries (entry = kc*8+nt)
    if (t0 < 512){
        int entry = t0 >> 5, nt = entry & 7, kc = entry >> 3, n = nt*8 + gg;
        float sn = g_nb[n]*rsqrtf(v_nb[n]+EPSBN);
        int k0 = kc*16 + 2*tt;
        float w0 = w_nb[(32+k0)*64+n]*sn,   w1 = w_nb[(32+k0+1)*64+n]*sn;
        float w2 = w_nb[(32+k0+8)*64+n]*sn, w3 = w_nb[(32+k0+9)*64+n]*sn;
        d_fragR2[t0] = make_uint2(pack_f16x2(w0,w1), pack_f16x2(w2,w3));
    }
    // fragGt + fragSc (bf16 3-split, K=32 -> kc 0..1): 512 entries each
    if (t0 < 512){
        int entry = t0 >> 5, nt = entry & 7, kc = entry >> 3, n = nt*8 + gg;
        int k0 = kc*16 + 2*tt;
        float sg = g_nb[n]*rsqrtf(v_nb[n]+EPSBN);
        float g0 = w_nb[k0*64+n]*sg,     g1 = w_nb[(k0+1)*64+n]*sg;
        float g2 = w_nb[(k0+8)*64+n]*sg, g3 = w_nb[(k0+9)*64+n]*sg;
        uint32_t h0,l0,h1,l1; split_pair(g0,g1,h0,l0); split_pair(g2,g3,h1,l1);
        d_fragGt[t0] = make_uint4(h0,h1,l0,l1);
        float ssn = g_sc[n]*rsqrtf(v_sc[n]+EPSBN);
        float s0 = w_sc[k0*32 + 0]*0.f; // placeholder avoided; real below
        (void)s0;
        float c0 = w_sc[k0*64+n]*ssn,     c1 = w_sc[(k0+1)*64+n]*ssn;
        float c2 = w_sc[(k0+8)*64+n]*ssn, c3 = w_sc[(k0+9)*64+n]*ssn;
        split_pair(c0,c1,h0,l0); split_pair(c2,c3,h1,l1);
        d_fragSc[t0] = make_uint4(h0,h1,l0,l1);
    }
    // fragS2 (fp16, prescaled by log2e): 1024 entries (entry = kc*8+nt, kc 0..3)
    {
        int entry = t0 >> 5, nt = entry & 7, kc = entry >> 3, n = nt*8 + gg;
        int k0 = kc*16 + 2*tt;
        float w0 = w_attn[k0*64+n]*LOG2E,     w1 = w_attn[(k0+1)*64+n]*LOG2E;
        float w2 = w_attn[(k0+8)*64+n]*LOG2E, w3 = w_attn[(k0+9)*64+n]*LOG2E;
        d_fragS2[t0] = make_uint2(pack_f16x2(w0,w1), pack_f16x2(w2,w3));
    }
    // fragOut (bf16 3-split): 1024 entries, folded w_out
    {
        int entry = t0 >> 5, nt = entry & 7, kc = entry >> 3, n = nt*8 + gg;
        float sn = g_out[n]*rsqrtf(v_out[n]+EPSBN);
        int k0 = kc*16 + 2*tt;
        float w0 = w_out[k0*64+n]*sn,     w1 = w_out[(k0+1)*64+n]*sn;
        float w2 = w_out[(k0+8)*64+n]*sn, w3 = w_out[(k0+9)*64+n]*sn;
        uint32_t h0,l0,h1,l1; split_pair(w0,w1,h0,l0); split_pair(w2,w3,h1,l1);
        d_fragOut[t0] = make_uint4(h0,h1,l0,l1);
    }
    // biases
    if (t0 < 64){
        int p = t0;
        float s = g_nb[p]*rsqrtf(v_nb[p]+EPSBN);
        d_bnb[p] = (b_nb[p]-m_nb[p])*s + be_nb[p];
        float so = g_out[p]*rsqrtf(v_out[p]+EPSBN);
        d_boutN[p] = (b_out[p]-m_out[p])*so + be_out[p];
        float ss = g_sc[p]*rsqrtf(v_sc[p]+EPSBN);
        d_bscN[p] = (b_sc[p]-m_sc[p])*ss + be_sc[p];
    }
    if (t0 < 32){
        int p = t0;
        float sr = g_raw[p]*rsqrtf(v_raw[p]+EPSBN);
        d_braw[p] = (b_raw[p]-m_raw[p])*sr + be_raw[p];
    }
}

// ---- Kernel 1 (HMMA): G = feature@Wtop' + bnb ; SC = feature@w_sc' + b_sc'. 16 pts/warp. ----
__global__ void __launch_bounds__(256) g_kernel(const float* __restrict__ feature)
{
    const int tid = threadIdx.x, lane = tid & 31, w = tid >> 5;
    const int g = lane >> 2, t = lane & 3;
    const int ptb = (blockIdx.x*8 + w)*16;

    const float2* F0 = (const float2*)feature + (size_t)(ptb+g)*16;
    const float2* F1 = (const float2*)feature + (size_t)(ptb+g+8)*16;

    float DG[8][4], DS[8][4];
    #pragma unroll
    for (int nt=0;nt<8;nt++){
        float2 bg = *(const float2*)&d_bnb[nt*8 + 2*t];
        float2 bs = *(const float2*)&d_bscN[nt*8 + 2*t];
        DG[nt][0]=bg.x; DG[nt][1]=bg.y; DG[nt][2]=bg.x; DG[nt][3]=bg.y;
        DS[nt][0]=bs.x; DS[nt][1]=bs.y; DS[nt][2]=bs.x; DS[nt][3]=bs.y;
    }
    uint32_t ah[4], al[4];
    #pragma unroll
    for (int kc=0;kc<2;kc++){
        float2 p0 = F0[kc*8 + t];
        float2 p1 = F1[kc*8 + t];
        float2 p2 = F0[kc*8 + t + 4];
        float2 p3 = F1[kc*8 + t + 4];
        split_pair(p0.x, p0.y, ah[0], al[0]);
        split_pair(p1.x, p1.y, ah[1], al[1]);
        split_pair(p2.x, p2.y, ah[2], al[2]);
        split_pair(p3.x, p3.y, ah[3], al[3]);
        #pragma unroll
        for (int nt=0;nt<8;nt++){
            mma3(DG[nt], ah, al, d_fragGt[(kc*8+nt)*32 + lane]);
            mma3(DS[nt], ah, al, d_fragSc[(kc*8+nt)*32 + lane]);
        }
    }
    #pragma unroll
    for (int nt=0;nt<8;nt++){
        int c = nt*8 + 2*t;
        *(float2*)&d_G[(size_t)(ptb+g)*64   + c] = make_float2(DG[nt][0], DG[nt][1]);
        *(float2*)&d_G[(size_t)(ptb+g+8)*64 + c] = make_float2(DG[nt][2], DG[nt][3]);
        *(float2*)&d_SC[(size_t)(ptb+g)*64   + c] = make_float2(DS[nt][0], DS[nt][1]);
        *(float2*)&d_SC[(size_t)(ptb+g+8)*64 + c] = make_float2(DS[nt][2], DS[nt][3]);
    }
}

// ---- Kernel 2: fused main. One warp/point; bf16 raw-mlp + fp16 2-split R/s. ----
__global__ void __launch_bounds__(128, 5) main_kernel(
    const float* __restrict__ raw,
    const int*   __restrict__ nbr)
{
    const int tid = threadIdx.x, lane = tid & 31, w = tid >> 5;
    const int g = lane >> 2, t = lane & 3;

    const int pt = blockIdx.x*4 + w;
    const int bbase = (pt >> 16) << 16;     // batch offset (N=65536)

    int idxv = 0;
    if (lane < 16) idxv = nbr[pt*16 + lane];
    const int jr0 = __shfl_sync(0xffffffffu, idxv, g);
    const int jr1 = __shfl_sync(0xffffffffu, idxv, g+8);

    // ---- raw A-frags straight from gmem (bf16 3-split) ----
    const float2* raw2 = (const float2*)raw + (size_t)pt*80;
    uint32_t ah[4], al[4];
    {
        float2 p0 = raw2[g*5 + t];
        float2 p1 = raw2[(g+8)*5 + t];
        float2 p2 = (t==0) ? raw2[g*5 + 4]     : make_float2(0.f,0.f);
        float2 p3 = (t==0) ? raw2[(g+8)*5 + 4] : make_float2(0.f,0.f);
        split_pair(p0.x, p0.y, ah[0], al[0]);
        split_pair(p1.x, p1.y, ah[1], al[1]);
        split_pair(p2.x, p2.y, ah[2], al[2]);
        split_pair(p3.x, p3.y, ah[3], al[3]);
    }

    // ---- gather G directly into hv accumulators (G carries bnb) ----
    float hv[8][4];
    {
        const float* G0 = d_G + (size_t)(bbase + jr0)*64;
        const float* G1 = d_G + (size_t)(bbase + jr1)*64;
        #pragma unroll
        for (int nt=0;nt<8;nt++){
            float2 a = *(const float2*)&G0[nt*8 + 2*t];
            float2 b = *(const float2*)&G1[nt*8 + 2*t];
            hv[nt][0]=a.x; hv[nt][1]=a.y; hv[nt][2]=b.x; hv[nt][3]=b.y;
        }
    }

    // ---- raw mlp: rmD(16x32) = raw(16x16) @ Wraw + braw; lrelu in place ----
    float rmD[4][4];
    #pragma unroll
    for (int nt=0;nt<4;nt++){
        float2 b = *(const float2*)&d_braw[nt*8 + 2*t];
        rmD[nt][0]=b.x; rmD[nt][1]=b.y; rmD[nt][2]=b.x; rmD[nt][3]=b.y;
    }
    #pragma unroll
    for (int nt=0;nt<4;nt++)
        mma3(rmD[nt], ah, al, d_fragRaw[nt*32 + lane]);
    #pragma unroll
    for (int nt=0;nt<4;nt++)
        #pragma unroll
        for (int i=0;i<4;i++) rmD[nt][i] = lrelu(rmD[nt][i]);

    // ---- R-GEMM (fp16 2-split): hv += rm(16x32) @ W_nbb ----
    #pragma unroll
    for (int kc=0;kc<2;kc++){
        dfrags_to_afrags_f16(rmD[2*kc], rmD[2*kc+1], ah, al);
        #pragma unroll
        for (int nt=0;nt<8;nt++)
            mma2(hv[nt], ah, al, d_fragR2[(kc*8+nt)*32 + lane]);
    }

    // ---- h = lrelu(hv), in place ----
    #pragma unroll
    for (int nt=0;nt<8;nt++)
        #pragma unroll
        for (int i=0;i<4;i++) hv[nt][i] = lrelu(hv[nt][i]);

    // ---- pre-split A-frags for the s-GEMM (all 4 kc, fp16) ----
    uint32_t sah[4][4], sal[4][4];
    #pragma unroll
    for (int kc=0;kc<4;kc++)
        dfrags_to_afrags_f16(hv[2*kc], hv[2*kc+1], sah[kc], sal[kc]);

    // ---- s-GEMM per nt (fp16 2-split, w_attn prescaled by log2e) + softmax partials ----
    float Kd[8], Kn[8];
    const bool gb0 = (lane & 4) != 0;
    #pragma unroll
    for (int nt=0;nt<8;nt++){
        float sd[4] = {0.f, 0.f, 0.f, 0.f};
        #pragma unroll
        for (int kc=0;kc<4;kc++)
            mma2(sd, sah[kc], sal[kc], d_fragS2[(kc*8+nt)*32 + lane]);
        float e0=exp2f(sd[0]), e1=exp2f(sd[1]);
        float e2=exp2f(sd[2]), e3=exp2f(sd[3]);
        float den0 = e0+e2, num0 = fmaf(e0, hv[nt][0], e2*hv[nt][2]);
        float den1 = e1+e3, num1 = fmaf(e1, hv[nt][1], e3*hv[nt][3]);
        float sdd = gb0 ? den0 : den1;
        float snn = gb0 ? num0 : num1;
        float rd = __shfl_xor_sync(0xffffffffu, sdd, 4);
        float rn = __shfl_xor_sync(0xffffffffu, snn, 4);
        Kd[nt] = (gb0 ? den1 : den0) + rd;
        Kn[nt] = (gb0 ? num1 : num0) + rn;
    }
    const bool gb1 = (lane & 8) != 0;
    float Ld[4], Ln[4];
    #pragma unroll
    for (int j=0;j<4;j++){
        float sd = gb1 ? Kd[j] : Kd[j+4];
        float sn = gb1 ? Kn[j] : Kn[j+4];
        float rd = __shfl_xor_sync(0xffffffffu, sd, 8);
        float rn = __shfl_xor_sync(0xffffffffu, sn, 8);
        Ld[j] = (gb1 ? Kd[j+4] : Kd[j]) + rd;
        Ln[j] = (gb1 ? Kn[j+4] : Kn[j]) + rn;
    }
    const bool gb2 = (lane & 16) != 0;
    #pragma unroll
    for (int j=0;j<2;j++){
        float sd = gb2 ? Ld[j] : Ld[j+2];
        float sn = gb2 ? Ln[j] : Ln[j+2];
        float rd = __shfl_xor_sync(0xffffffffu, sd, 16);
        float rn = __shfl_xor_sync(0xffffffffu, sn, 16);
        float md = (gb2 ? Ld[j+2] : Ld[j]) + rd;
        float mn = (gb2 ? Ln[j+2] : Ln[j]) + rn;
        int nt = j + (gb2 ? 2 : 0) + (gb1 ? 4 : 0);
        int c  = nt*8 + 2*t + (gb0 ? 1 : 0);
        d_P[(size_t)pt*64 + c] = __fdividef(mn, md);
    }
}

// ---- Kernel 3: out = lrelu(SC + pooled @ w_out' + b_out'). N-split: 4 nt/warp. ----
__global__ void __launch_bounds__(256) out_kernel(float* __restrict__ outp)
{
    const int tid = threadIdx.x, lane = tid & 31, w = tid >> 5;
    const int g = lane >> 2, t = lane & 3;
    const int par = blockIdx.x & 1;                 // N half: nt in [4*par, 4*par+4)
    const int ptb = ((blockIdx.x >> 1)*8 + w)*16;

    const float2* P0 = (const float2*)(d_P + (size_t)(ptb+g)*64);
    const float2* P1 = (const float2*)(d_P + (size_t)(ptb+g+8)*64);

    float D[4][4];
    #pragma unroll
    for (int nt=0;nt<4;nt++){
        float2 b = *(const float2*)&d_boutN[(nt+4*par)*8 + 2*t];
        D[nt][0]=b.x; D[nt][1]=b.y; D[nt][2]=b.x; D[nt][3]=b.y;
    }
    uint32_t ah[4], al[4];
    #pragma unroll
    for (int kc=0;kc<4;kc++){
        float2 p0 = P0[kc*8 + t];
        float2 p1 = P1[kc*8 + t];
        float2 p2 = P0[kc*8 + t + 4];
        float2 p3 = P1[kc*8 + t + 4];
        split_pair(p0.x, p0.y, ah[0], al[0]);
        split_pair(p1.x, p1.y, ah[1], al[1]);
        split_pair(p2.x, p2.y, ah[2], al[2]);
        split_pair(p3.x, p3.y, ah[3], al[3]);
        #pragma unroll
        for (int nt=0;nt<4;nt++)
            mma3(D[nt], ah, al, d_fragOut[(kc*8 + nt + 4*par)*32 + lane]);
    }
    const float* S0 = d_SC + (size_t)(ptb+g)*64;
    const float* S1 = d_SC + (size_t)(ptb+g+8)*64;
    #pragma unroll
    for (int nt=0;nt<4;nt++){
        int c = (nt+4*par)*8 + 2*t;
        float2 s0 = *(const float2*)&S0[c];
        float2 s1 = *(const float2*)&S1[c];
        *(float2*)&outp[(size_t)(ptb+g)*64   + c] =
            make_float2(lrelu(D[nt][0] + s0.x), lrelu(D[nt][1] + s0.y));
        *(float2*)&outp[(size_t)(ptb+g+8)*64 + c] =
            make_float2(lrelu(D[nt][2] + s1.x), lrelu(D[nt][3] + s1.y));
    }
}

extern "C" void kernel_launch(void* const* d_in, const int* in_sizes, int n_in,
                              void* d_out, int out_size)
{
    const float* feature = (const float*)d_in[0];
    const float* raw     = (const float*)d_in[1];
    const int*   nbr     = (const int*)  d_in[2];

    fold_kernel<<<1, 1024>>>(
        (const float*)d_in[3],  (const float*)d_in[4],  (const float*)d_in[5],
        (const float*)d_in[6],  (const float*)d_in[7],  (const float*)d_in[8],
        (const float*)d_in[9],  (const float*)d_in[10], (const float*)d_in[11],
        (const float*)d_in[12], (const float*)d_in[13], (const float*)d_in[14],
        (const float*)d_in[15],
        (const float*)d_in[16], (const float*)d_in[17], (const float*)d_in[18],
        (const float*)d_in[19], (const float*)d_in[20], (const float*)d_in[21],
        (const float*)d_in[22], (const float*)d_in[23], (const float*)d_in[24],
        (const float*)d_in[25], (const float*)d_in[26], (const float*)d_in[27]);

    g_kernel<<<NPTS/(16*8), 256>>>(feature);

    main_kernel<<<NPTS/4, 128>>>(raw, nbr);

    out_kernel<<<NPTS/(16*8)*2, 256>>>((float*)d_out);
}